// round 1
// baseline (speedup 1.0000x reference)
#include <cuda_runtime.h>
#include <math_constants.h>

// Problem constants
#define BB 8
#define SS 1024
#define EE 1024
#define HH 16
#define DD 64

// Scratch (device globals — no allocation allowed)
__device__ float g_Q[BB * SS * EE];
__device__ float g_K[BB * SS * EE];
__device__ float g_V[BB * SS * EE];
__device__ float g_AO[BB * SS * EE];

// ---------------------------------------------------------------------------
// SGEMM with bias: C[M,N] = A[M,K] @ B[K,N] + bias[N]
// BM=128, BN=128, BK=16, 256 threads, 8x8 per-thread microtile (split 4+4).
// ---------------------------------------------------------------------------
#define BM 128
#define BN 128
#define BK 16

__global__ __launch_bounds__(256) void sgemm_bias_kernel(
    const float* __restrict__ A, const float* __restrict__ Bw,
    const float* __restrict__ bias, float* __restrict__ C,
    int M, int N, int K)
{
    __shared__ float As[BK][BM];   // stored transposed: As[k][m]
    __shared__ float Bs[BK][BN];

    const int tid  = threadIdx.x;
    const int brow = blockIdx.y * BM;
    const int bcol = blockIdx.x * BN;

    const int ty = tid >> 4;     // 0..15  -> rows ty*4 and 64+ty*4
    const int tx = tid & 15;     // 0..15  -> cols tx*4 and 64+tx*4

    // A-tile loads: 128 rows x 16 k = 512 float4; 2 per thread
    const int arow = tid >> 2;         // 0..63
    const int acol = (tid & 3) * 4;    // 0,4,8,12
    // B-tile loads: 16 k x 128 n = 512 float4; 2 per thread
    const int brl = tid >> 5;          // 0..7
    const int bcl = (tid & 31) * 4;    // 0..124

    float acc[8][8];
    #pragma unroll
    for (int i = 0; i < 8; i++)
        #pragma unroll
        for (int j = 0; j < 8; j++) acc[i][j] = 0.f;

    for (int k0 = 0; k0 < K; k0 += BK) {
        #pragma unroll
        for (int p = 0; p < 2; p++) {
            int r = arow + p * 64;
            float4 a = *(const float4*)&A[(size_t)(brow + r) * K + k0 + acol];
            As[acol + 0][r] = a.x;
            As[acol + 1][r] = a.y;
            As[acol + 2][r] = a.z;
            As[acol + 3][r] = a.w;
        }
        #pragma unroll
        for (int p = 0; p < 2; p++) {
            int r = brl + p * 8;
            *(float4*)&Bs[r][bcl] =
                *(const float4*)&Bw[(size_t)(k0 + r) * N + bcol + bcl];
        }
        __syncthreads();

        #pragma unroll
        for (int k = 0; k < BK; k++) {
            float4 a0 = *(const float4*)&As[k][ty * 4];
            float4 a1 = *(const float4*)&As[k][64 + ty * 4];
            float4 b0 = *(const float4*)&Bs[k][tx * 4];
            float4 b1 = *(const float4*)&Bs[k][64 + tx * 4];
            float ra[8] = {a0.x, a0.y, a0.z, a0.w, a1.x, a1.y, a1.z, a1.w};
            float rb[8] = {b0.x, b0.y, b0.z, b0.w, b1.x, b1.y, b1.z, b1.w};
            #pragma unroll
            for (int i = 0; i < 8; i++)
                #pragma unroll
                for (int j = 0; j < 8; j++)
                    acc[i][j] += ra[i] * rb[j];
        }
        __syncthreads();
    }

    // Writeback + bias
    #pragma unroll
    for (int ii = 0; ii < 2; ii++) {
        #pragma unroll
        for (int i = 0; i < 4; i++) {
            int row = brow + ii * 64 + ty * 4 + i;
            #pragma unroll
            for (int jj = 0; jj < 2; jj++) {
                int col = bcol + jj * 64 + tx * 4;
                float4 bb = *(const float4*)&bias[col];
                float4 o;
                o.x = acc[ii * 4 + i][jj * 4 + 0] + bb.x;
                o.y = acc[ii * 4 + i][jj * 4 + 1] + bb.y;
                o.z = acc[ii * 4 + i][jj * 4 + 2] + bb.z;
                o.w = acc[ii * 4 + i][jj * 4 + 3] + bb.w;
                *(float4*)&C[(size_t)row * N + col] = o;
            }
        }
    }
}

// ---------------------------------------------------------------------------
// RoPE applied in-place to Q and K.
// Layout: [b, s, h, d] flattened as (b*S+s)*E + h*D + d.
// out[:32] = t1*cos - t2*sin ; out[32:] = t2*cos + t1*sin ; freqs (S, 32)
// ---------------------------------------------------------------------------
__global__ void rope_kernel(float* __restrict__ Q, float* __restrict__ K,
                            const float* __restrict__ freqs)
{
    int idx = blockIdx.x * blockDim.x + threadIdx.x;   // over B*S*H*32 = 4M
    if (idx >= BB * SS * HH * 32) return;
    int dh = idx & 31;
    int h  = (idx >> 5) & (HH - 1);
    int bs = idx >> 9;              // b*S + s
    int s  = bs & (SS - 1);

    float f = freqs[s * 32 + dh];
    float sf, cf;
    sincosf(f, &sf, &cf);

    size_t base = (size_t)bs * EE + h * DD + dh;
    float q1 = Q[base], q2 = Q[base + 32];
    Q[base]      = q1 * cf - q2 * sf;
    Q[base + 32] = q2 * cf + q1 * sf;
    float k1 = K[base], k2 = K[base + 32];
    K[base]      = k1 * cf - k2 * sf;
    K[base + 32] = k2 * cf + k1 * sf;
}

// ---------------------------------------------------------------------------
// Flash-style attention, fp32.
// Grid: (S/BQ, B*H). Block: 256 threads (16 row-groups x 16 col-groups).
// BQ=128 queries, BKV=64 keys per tile, D=64.
// Each thread: 8 rows x 4 cols of scores / output.
// Shared tiles padded to stride 65 for conflict mitigation.
// ---------------------------------------------------------------------------
#define BQ 128
#define BKV 64
#define PAD 65

__global__ __launch_bounds__(256) void attn_kernel(
    const float* __restrict__ Qg, const float* __restrict__ Kg,
    const float* __restrict__ Vg, float* __restrict__ Og)
{
    extern __shared__ float sm[];
    float* Qs = sm;                        // [BQ][PAD]
    float* Ks = Qs + BQ * PAD;             // [BKV][PAD]
    float* Vs = Ks + BKV * PAD;            // [BKV][PAD]
    float* Ps = Vs + BKV * PAD;            // [BQ][PAD]

    const int tid = threadIdx.x;
    const int ty  = tid >> 4;      // 0..15 -> rows ty*8 .. ty*8+7
    const int tx  = tid & 15;      // 0..15 -> cols tx*4 .. tx*4+3

    const int bh = blockIdx.y;
    const int b  = bh >> 4;
    const int h  = bh & (HH - 1);
    const int q0 = blockIdx.x * BQ;

    const float* Qb = Qg + (size_t)b * SS * EE + h * DD;
    const float* Kb = Kg + (size_t)b * SS * EE + h * DD;
    const float* Vb = Vg + (size_t)b * SS * EE + h * DD;

    // Load Q tile (128 x 64), coalesced, scalar stores into padded smem
    {
        int col = (tid & 15) * 4;
        int r0  = tid >> 4;
        #pragma unroll
        for (int i = 0; i < 8; i++) {
            int r = i * 16 + r0;
            float4 v = *(const float4*)&Qb[(size_t)(q0 + r) * EE + col];
            Qs[r * PAD + col + 0] = v.x;
            Qs[r * PAD + col + 1] = v.y;
            Qs[r * PAD + col + 2] = v.z;
            Qs[r * PAD + col + 3] = v.w;
        }
    }

    float m[8], l[8], acc[8][4];
    #pragma unroll
    for (int i = 0; i < 8; i++) {
        m[i] = -CUDART_INF_F;
        l[i] = 0.f;
        #pragma unroll
        for (int j = 0; j < 4; j++) acc[i][j] = 0.f;
    }

    const float scale = 0.125f;  // 1/sqrt(64)

    for (int k0 = 0; k0 < SS; k0 += BKV) {
        __syncthreads();
        // Load K,V tiles (64 x 64 each)
        {
            int col = (tid & 15) * 4;
            int r0  = tid >> 4;
            #pragma unroll
            for (int i = 0; i < 4; i++) {
                int r = i * 16 + r0;
                float4 kv = *(const float4*)&Kb[(size_t)(k0 + r) * EE + col];
                Ks[r * PAD + col + 0] = kv.x;
                Ks[r * PAD + col + 1] = kv.y;
                Ks[r * PAD + col + 2] = kv.z;
                Ks[r * PAD + col + 3] = kv.w;
                float4 vv = *(const float4*)&Vb[(size_t)(k0 + r) * EE + col];
                Vs[r * PAD + col + 0] = vv.x;
                Vs[r * PAD + col + 1] = vv.y;
                Vs[r * PAD + col + 2] = vv.z;
                Vs[r * PAD + col + 3] = vv.w;
            }
        }
        __syncthreads();

        // Scores: sc[8][4] = Q(rows) . K(cols)
        float sc[8][4];
        #pragma unroll
        for (int i = 0; i < 8; i++)
            #pragma unroll
            for (int j = 0; j < 4; j++) sc[i][j] = 0.f;

        #pragma unroll 4
        for (int d = 0; d < DD; d++) {
            float kb[4];
            #pragma unroll
            for (int j = 0; j < 4; j++)
                kb[j] = Ks[(tx * 4 + j) * PAD + d];
            #pragma unroll
            for (int i = 0; i < 8; i++) {
                float qa = Qs[(ty * 8 + i) * PAD + d];
                #pragma unroll
                for (int j = 0; j < 4; j++)
                    sc[i][j] += qa * kb[j];
            }
        }

        // Online softmax update per row
        #pragma unroll
        for (int i = 0; i < 8; i++) {
            #pragma unroll
            for (int j = 0; j < 4; j++) sc[i][j] *= scale;

            float rmax = fmaxf(fmaxf(sc[i][0], sc[i][1]),
                               fmaxf(sc[i][2], sc[i][3]));
            #pragma unroll
            for (int o = 8; o >= 1; o >>= 1)
                rmax = fmaxf(rmax, __shfl_xor_sync(0xffffffffu, rmax, o));

            float mnew = fmaxf(m[i], rmax);
            float corr = __expf(m[i] - mnew);
            float rsum = 0.f;
            #pragma unroll
            for (int j = 0; j < 4; j++) {
                float p = __expf(sc[i][j] - mnew);
                Ps[(ty * 8 + i) * PAD + tx * 4 + j] = p;
                rsum += p;
            }
            #pragma unroll
            for (int o = 8; o >= 1; o >>= 1)
                rsum += __shfl_xor_sync(0xffffffffu, rsum, o);

            l[i] = l[i] * corr + rsum;
            m[i] = mnew;
            #pragma unroll
            for (int j = 0; j < 4; j++) acc[i][j] *= corr;
        }
        // Ps rows of this row-group are written & read only by this half-warp
        __syncwarp();

        // O += P @ V
        #pragma unroll 4
        for (int kk = 0; kk < BKV; kk++) {
            float vb[4];
            #pragma unroll
            for (int j = 0; j < 4; j++)
                vb[j] = Vs[kk * PAD + tx * 4 + j];
            #pragma unroll
            for (int i = 0; i < 8; i++) {
                float p = Ps[(ty * 8 + i) * PAD + kk];
                #pragma unroll
                for (int j = 0; j < 4; j++)
                    acc[i][j] += p * vb[j];
            }
        }
    }

    // Epilogue: normalize and store
    #pragma unroll
    for (int i = 0; i < 8; i++) {
        float inv = 1.0f / l[i];
        int r = q0 + ty * 8 + i;
        float4 o;
        o.x = acc[i][0] * inv;
        o.y = acc[i][1] * inv;
        o.z = acc[i][2] * inv;
        o.w = acc[i][3] * inv;
        *(float4*)&Og[((size_t)b * SS + r) * EE + h * DD + tx * 4] = o;
    }
}

// ---------------------------------------------------------------------------
// Launch
// ---------------------------------------------------------------------------
extern "C" void kernel_launch(void* const* d_in, const int* in_sizes, int n_in,
                              void* d_out, int out_size)
{
    const float* X   = (const float*)d_in[0];
    const float* rot = (const float*)d_in[1];
    const float* wq  = (const float*)d_in[2];
    const float* bq  = (const float*)d_in[3];
    const float* wk  = (const float*)d_in[4];
    const float* bk  = (const float*)d_in[5];
    const float* wv  = (const float*)d_in[6];
    const float* bv  = (const float*)d_in[7];
    const float* wo  = (const float*)d_in[8];
    const float* bo  = (const float*)d_in[9];
    float* out = (float*)d_out;

    float *Qp, *Kp, *Vp, *AOp;
    cudaGetSymbolAddress((void**)&Qp,  g_Q);
    cudaGetSymbolAddress((void**)&Kp,  g_K);
    cudaGetSymbolAddress((void**)&Vp,  g_V);
    cudaGetSymbolAddress((void**)&AOp, g_AO);

    const int M = BB * SS;           // 8192
    dim3 gemm_grid(EE / BN, M / BM); // (8, 64)

    sgemm_bias_kernel<<<gemm_grid, 256>>>(X, wq, bq, Qp, M, EE, EE);
    sgemm_bias_kernel<<<gemm_grid, 256>>>(X, wk, bk, Kp, M, EE, EE);
    sgemm_bias_kernel<<<gemm_grid, 256>>>(X, wv, bv, Vp, M, EE, EE);

    int rope_total = BB * SS * HH * 32;
    rope_kernel<<<(rope_total + 255) / 256, 256>>>(Qp, Kp, rot);

    const int ATTN_SMEM = (BQ * PAD + BKV * PAD + BKV * PAD + BQ * PAD) * 4;
    cudaFuncSetAttribute(attn_kernel,
                         cudaFuncAttributeMaxDynamicSharedMemorySize, ATTN_SMEM);
    attn_kernel<<<dim3(SS / BQ, BB * HH), 256, ATTN_SMEM>>>(Qp, Kp, Vp, AOp);

    sgemm_bias_kernel<<<gemm_grid, 256>>>(AOp, wo, bo, out, M, EE, EE);
}

// round 3
// speedup vs baseline: 1.4283x; 1.4283x over previous
#include <cuda_runtime.h>
#include <cuda_bf16.h>
#include <math_constants.h>
#include <cstdint>

// Problem constants
#define BB 8
#define SS 1024
#define EE 1024
#define HH 16
#define DD 64
#define MM (BB * SS)   // 8192

// ---------------------------------------------------------------------------
// Scratch (device globals — no allocation allowed)
// ---------------------------------------------------------------------------
__device__ float g_Q[MM * EE];
__device__ float g_K[MM * EE];
__device__ float g_V[MM * EE];
__device__ float g_AO[MM * EE];
__device__ __nv_bfloat16 g_Xhi[MM * EE];
__device__ __nv_bfloat16 g_Xlo[MM * EE];
__device__ __nv_bfloat16 g_AOhi[MM * EE];
__device__ __nv_bfloat16 g_AOlo[MM * EE];
// Transposed weights: [N][K] bf16, hi/lo split. Index: 0=q,1=k,2=v,3=o
__device__ __nv_bfloat16 g_Whi[4][EE * EE];
__device__ __nv_bfloat16 g_Wlo[4][EE * EE];

// ---------------------------------------------------------------------------
// Helpers
// ---------------------------------------------------------------------------
__device__ __forceinline__ uint32_t smem_u32(const void* p) {
    uint32_t a;
    asm("{ .reg .u64 t; cvta.to.shared.u64 t, %1; cvt.u32.u64 %0, t; }"
        : "=r"(a) : "l"(p));
    return a;
}

__device__ __forceinline__ void ldsm_x4(uint32_t* r, uint32_t addr) {
    asm volatile("ldmatrix.sync.aligned.m8n8.x4.shared.b16 {%0,%1,%2,%3}, [%4];"
                 : "=r"(r[0]), "=r"(r[1]), "=r"(r[2]), "=r"(r[3]) : "r"(addr));
}

__device__ __forceinline__ void mma_bf16(float* d, const uint32_t* a,
                                         uint32_t b0, uint32_t b1) {
    asm volatile(
        "mma.sync.aligned.m16n8k16.row.col.f32.bf16.bf16.f32 "
        "{%0,%1,%2,%3}, {%4,%5,%6,%7}, {%8,%9}, {%0,%1,%2,%3};"
        : "+f"(d[0]), "+f"(d[1]), "+f"(d[2]), "+f"(d[3])
        : "r"(a[0]), "r"(a[1]), "r"(a[2]), "r"(a[3]), "r"(b0), "r"(b1));
}

#define CP_ASYNC16(dst, src) \
    asm volatile("cp.async.cg.shared.global [%0], [%1], 16;\n" \
                 :: "r"(dst), "l"(src) : "memory")
#define CP_COMMIT() asm volatile("cp.async.commit_group;\n" ::: "memory")

// ---------------------------------------------------------------------------
// fp32 -> bf16 hi/lo split (no transpose)
// ---------------------------------------------------------------------------
__global__ void split_convert_kernel(const float* __restrict__ X,
                                     __nv_bfloat16* __restrict__ hi,
                                     __nv_bfloat16* __restrict__ lo, int n4)
{
    int i = blockIdx.x * blockDim.x + threadIdx.x;
    if (i >= n4) return;
    float4 v = *(const float4*)&X[i * 4];
    float vv[4] = {v.x, v.y, v.z, v.w};
    #pragma unroll
    for (int j = 0; j < 4; j++) {
        __nv_bfloat16 h = __float2bfloat16(vv[j]);
        float r = vv[j] - __bfloat162float(h);
        hi[i * 4 + j] = h;
        lo[i * 4 + j] = __float2bfloat16(r);
    }
}

// ---------------------------------------------------------------------------
// Weight transpose + split: W[K][N] fp32 -> Wt[N][K] bf16 hi/lo
// ---------------------------------------------------------------------------
__global__ __launch_bounds__(1024) void transpose_split_kernel(
    const float* __restrict__ W,
    __nv_bfloat16* __restrict__ Whi, __nv_bfloat16* __restrict__ Wlo)
{
    __shared__ float t[32][33];
    int k = blockIdx.y * 32 + threadIdx.y;
    int n = blockIdx.x * 32 + threadIdx.x;
    t[threadIdx.y][threadIdx.x] = W[(size_t)k * EE + n];
    __syncthreads();
    int nn = blockIdx.x * 32 + threadIdx.y;
    int kk = blockIdx.y * 32 + threadIdx.x;
    float v = t[threadIdx.x][threadIdx.y];
    __nv_bfloat16 h = __float2bfloat16(v);
    float r = v - __bfloat162float(h);
    Whi[(size_t)nn * EE + kk] = h;
    Wlo[(size_t)nn * EE + kk] = __float2bfloat16(r);
}

// ---------------------------------------------------------------------------
// HMMA bf16 3-pass split GEMM:
//   C[M,N] = Ahi@Bhi^T + Ahi@Blo^T + Alo@Bhi^T + bias
// A: [M,K] bf16 row-major, B: [N,K] bf16 row-major (both K-major).
// CTA tile 128x128, BK=32, 256 threads (8 warps, 2x4), warp tile 64x32.
// 3-stage cp.async pipeline. Smem rows padded to 40 halves (80 B).
// ---------------------------------------------------------------------------
#define BKG 32
#define NIT (EE / BKG)          // 32
#define ROWB 80                 // bytes per smem row (40 halves)
#define MATB (128 * ROWB)       // 10240 B per matrix tile
#define OAH 0
#define OAL (1 * MATB)
#define OBH (2 * MATB)
#define OBL (3 * MATB)
#define STGB (4 * MATB)         // 40960 B per stage
#define GSTAGES 3
#define GEMM_SMEM (GSTAGES * STGB)  // 122880 B

__global__ __launch_bounds__(256) void gemm_hmma_kernel(
    const __nv_bfloat16* __restrict__ Ahi, const __nv_bfloat16* __restrict__ Alo,
    const __nv_bfloat16* __restrict__ Bhi, const __nv_bfloat16* __restrict__ Blo,
    const float* __restrict__ bias, float* __restrict__ C)
{
    extern __shared__ char smraw[];
    const uint32_t sb = smem_u32(smraw);
    const int tid  = threadIdx.x;
    const int wid  = tid >> 5;
    const int lane = tid & 31;
    const int m0 = blockIdx.y * 128;
    const int n0 = blockIdx.x * 128;
    const int wm = (wid & 1) * 64;        // warp row offset
    const int wn = (wid >> 1) * 32;       // warp col offset

    // Global load mapping: per matrix, thread covers rows (tid>>2, +64),
    // 16B chunk (tid&3).
    const int lr = tid >> 2;
    const int lc = tid & 3;
    const __nv_bfloat16* gsrc[4] = {
        Ahi + (size_t)(m0 + lr) * EE + lc * 8,
        Alo + (size_t)(m0 + lr) * EE + lc * 8,
        Bhi + (size_t)(n0 + lr) * EE + lc * 8,
        Blo + (size_t)(n0 + lr) * EE + lc * 8
    };
    const uint32_t dst0 = sb + lr * ROWB + lc * 16;

    // ldmatrix per-thread base offsets
    const uint32_t a_off = (wm + (lane & 15)) * ROWB + (lane >> 4) * 16;
    const uint32_t b_off = (wn + ((lane >> 4) << 3) + (lane & 7)) * ROWB
                         + ((lane >> 3) & 1) * 16;

    float d[4][4][4];
    #pragma unroll
    for (int mt = 0; mt < 4; mt++)
        #pragma unroll
        for (int nt = 0; nt < 4; nt++)
            #pragma unroll
            for (int i = 0; i < 4; i++) d[mt][nt][i] = 0.f;

    // Prologue: stages 0, 1
    #pragma unroll
    for (int s = 0; s < 2; s++) {
        #pragma unroll
        for (int mat = 0; mat < 4; mat++) {
            #pragma unroll
            for (int p = 0; p < 2; p++) {
                uint32_t dst = dst0 + s * STGB + mat * MATB + p * 64 * ROWB;
                const void* g = gsrc[mat] + (size_t)p * 64 * EE + s * BKG;
                CP_ASYNC16(dst, g);
            }
        }
        CP_COMMIT();
    }

    for (int it = 0; it < NIT; it++) {
        if (it < NIT - 2)
            asm volatile("cp.async.wait_group 1;\n" ::: "memory");
        else
            asm volatile("cp.async.wait_group 0;\n" ::: "memory");
        __syncthreads();

        // Issue stage it+2
        if (it + 2 < NIT) {
            int s = (it + 2) % GSTAGES;
            int k0 = (it + 2) * BKG;
            #pragma unroll
            for (int mat = 0; mat < 4; mat++) {
                #pragma unroll
                for (int p = 0; p < 2; p++) {
                    uint32_t dst = dst0 + s * STGB + mat * MATB + p * 64 * ROWB;
                    const void* g = gsrc[mat] + (size_t)p * 64 * EE + k0;
                    CP_ASYNC16(dst, g);
                }
            }
            CP_COMMIT();
        }

        const uint32_t st = sb + (it % GSTAGES) * STGB;
        #pragma unroll
        for (int kc = 0; kc < 2; kc++) {
            uint32_t ah[4][4], al[4][4], bh[2][4], bl[2][4];
            #pragma unroll
            for (int mt = 0; mt < 4; mt++) {
                ldsm_x4(ah[mt], st + OAH + a_off + mt * 16 * ROWB + kc * 32);
                ldsm_x4(al[mt], st + OAL + a_off + mt * 16 * ROWB + kc * 32);
            }
            #pragma unroll
            for (int np = 0; np < 2; np++) {
                ldsm_x4(bh[np], st + OBH + b_off + np * 16 * ROWB + kc * 32);
                ldsm_x4(bl[np], st + OBL + b_off + np * 16 * ROWB + kc * 32);
            }
            #pragma unroll
            for (int mt = 0; mt < 4; mt++) {
                #pragma unroll
                for (int nt = 0; nt < 4; nt++) {
                    int np = nt >> 1, sc = (nt & 1) * 2;
                    mma_bf16(d[mt][nt], ah[mt], bh[np][sc], bh[np][sc + 1]);
                    mma_bf16(d[mt][nt], ah[mt], bl[np][sc], bl[np][sc + 1]);
                    mma_bf16(d[mt][nt], al[mt], bh[np][sc], bh[np][sc + 1]);
                }
            }
        }
        __syncthreads();
    }

    // Epilogue: bias add + store (fp32)
    #pragma unroll
    for (int mt = 0; mt < 4; mt++) {
        int r = m0 + wm + mt * 16 + (lane >> 2);
        #pragma unroll
        for (int nt = 0; nt < 4; nt++) {
            int c = n0 + wn + nt * 8 + (lane & 3) * 2;
            float2 bb = *(const float2*)&bias[c];
            float2 o0 = {d[mt][nt][0] + bb.x, d[mt][nt][1] + bb.y};
            float2 o1 = {d[mt][nt][2] + bb.x, d[mt][nt][3] + bb.y};
            *(float2*)&C[(size_t)r * EE + c] = o0;
            *(float2*)&C[(size_t)(r + 8) * EE + c] = o1;
        }
    }
}

// ---------------------------------------------------------------------------
// RoPE applied in-place to Q and K (fp32). Layout (b*S+s)*E + h*D + d.
// ---------------------------------------------------------------------------
__global__ void rope_kernel(float* __restrict__ Q, float* __restrict__ K,
                            const float* __restrict__ freqs)
{
    int idx = blockIdx.x * blockDim.x + threadIdx.x;
    if (idx >= BB * SS * HH * 32) return;
    int dh = idx & 31;
    int bs = idx >> 9;
    int s  = bs & (SS - 1);

    float f = freqs[s * 32 + dh];
    float sf, cf;
    sincosf(f, &sf, &cf);

    int h = (idx >> 5) & (HH - 1);
    size_t base = (size_t)bs * EE + h * DD + dh;
    float q1 = Q[base], q2 = Q[base + 32];
    Q[base]      = q1 * cf - q2 * sf;
    Q[base + 32] = q2 * cf + q1 * sf;
    float k1 = K[base], k2 = K[base + 32];
    K[base]      = k1 * cf - k2 * sf;
    K[base + 32] = k2 * cf + k1 * sf;
}

// ---------------------------------------------------------------------------
// Flash-style attention, fp32 (unchanged)
// ---------------------------------------------------------------------------
#define BQ 128
#define BKV 64
#define PAD 65

__global__ __launch_bounds__(256) void attn_kernel(
    const float* __restrict__ Qg, const float* __restrict__ Kg,
    const float* __restrict__ Vg, float* __restrict__ Og)
{
    extern __shared__ float sm[];
    float* Qs = sm;
    float* Ks = Qs + BQ * PAD;
    float* Vs = Ks + BKV * PAD;
    float* Ps = Vs + BKV * PAD;

    const int tid = threadIdx.x;
    const int ty  = tid >> 4;
    const int tx  = tid & 15;

    const int bh = blockIdx.y;
    const int b  = bh >> 4;
    const int h  = bh & (HH - 1);
    const int q0 = blockIdx.x * BQ;

    const float* Qb = Qg + (size_t)b * SS * EE + h * DD;
    const float* Kb = Kg + (size_t)b * SS * EE + h * DD;
    const float* Vb = Vg + (size_t)b * SS * EE + h * DD;

    {
        int col = (tid & 15) * 4;
        int r0  = tid >> 4;
        #pragma unroll
        for (int i = 0; i < 8; i++) {
            int r = i * 16 + r0;
            float4 v = *(const float4*)&Qb[(size_t)(q0 + r) * EE + col];
            Qs[r * PAD + col + 0] = v.x;
            Qs[r * PAD + col + 1] = v.y;
            Qs[r * PAD + col + 2] = v.z;
            Qs[r * PAD + col + 3] = v.w;
        }
    }

    float m[8], l[8], acc[8][4];
    #pragma unroll
    for (int i = 0; i < 8; i++) {
        m[i] = -CUDART_INF_F;
        l[i] = 0.f;
        #pragma unroll
        for (int j = 0; j < 4; j++) acc[i][j] = 0.f;
    }

    const float scale = 0.125f;

    for (int k0 = 0; k0 < SS; k0 += BKV) {
        __syncthreads();
        {
            int col = (tid & 15) * 4;
            int r0  = tid >> 4;
            #pragma unroll
            for (int i = 0; i < 4; i++) {
                int r = i * 16 + r0;
                float4 kv = *(const float4*)&Kb[(size_t)(k0 + r) * EE + col];
                Ks[r * PAD + col + 0] = kv.x;
                Ks[r * PAD + col + 1] = kv.y;
                Ks[r * PAD + col + 2] = kv.z;
                Ks[r * PAD + col + 3] = kv.w;
                float4 vv = *(const float4*)&Vb[(size_t)(k0 + r) * EE + col];
                Vs[r * PAD + col + 0] = vv.x;
                Vs[r * PAD + col + 1] = vv.y;
                Vs[r * PAD + col + 2] = vv.z;
                Vs[r * PAD + col + 3] = vv.w;
            }
        }
        __syncthreads();

        float sc[8][4];
        #pragma unroll
        for (int i = 0; i < 8; i++)
            #pragma unroll
            for (int j = 0; j < 4; j++) sc[i][j] = 0.f;

        #pragma unroll 4
        for (int d = 0; d < DD; d++) {
            float kb[4];
            #pragma unroll
            for (int j = 0; j < 4; j++)
                kb[j] = Ks[(tx * 4 + j) * PAD + d];
            #pragma unroll
            for (int i = 0; i < 8; i++) {
                float qa = Qs[(ty * 8 + i) * PAD + d];
                #pragma unroll
                for (int j = 0; j < 4; j++)
                    sc[i][j] += qa * kb[j];
            }
        }

        #pragma unroll
        for (int i = 0; i < 8; i++) {
            #pragma unroll
            for (int j = 0; j < 4; j++) sc[i][j] *= scale;

            float rmax = fmaxf(fmaxf(sc[i][0], sc[i][1]),
                               fmaxf(sc[i][2], sc[i][3]));
            #pragma unroll
            for (int o = 8; o >= 1; o >>= 1)
                rmax = fmaxf(rmax, __shfl_xor_sync(0xffffffffu, rmax, o));

            float mnew = fmaxf(m[i], rmax);
            float corr = __expf(m[i] - mnew);
            float rsum = 0.f;
            #pragma unroll
            for (int j = 0; j < 4; j++) {
                float p = __expf(sc[i][j] - mnew);
                Ps[(ty * 8 + i) * PAD + tx * 4 + j] = p;
                rsum += p;
            }
            #pragma unroll
            for (int o = 8; o >= 1; o >>= 1)
                rsum += __shfl_xor_sync(0xffffffffu, rsum, o);

            l[i] = l[i] * corr + rsum;
            m[i] = mnew;
            #pragma unroll
            for (int j = 0; j < 4; j++) acc[i][j] *= corr;
        }
        __syncwarp();

        #pragma unroll 4
        for (int kk = 0; kk < BKV; kk++) {
            float vb[4];
            #pragma unroll
            for (int j = 0; j < 4; j++)
                vb[j] = Vs[kk * PAD + tx * 4 + j];
            #pragma unroll
            for (int i = 0; i < 8; i++) {
                float p = Ps[(ty * 8 + i) * PAD + kk];
                #pragma unroll
                for (int j = 0; j < 4; j++)
                    acc[i][j] += p * vb[j];
            }
        }
    }

    #pragma unroll
    for (int i = 0; i < 8; i++) {
        float inv = 1.0f / l[i];
        int r = q0 + ty * 8 + i;
        float4 o;
        o.x = acc[i][0] * inv;
        o.y = acc[i][1] * inv;
        o.z = acc[i][2] * inv;
        o.w = acc[i][3] * inv;
        *(float4*)&Og[((size_t)b * SS + r) * EE + h * DD + tx * 4] = o;
    }
}

// ---------------------------------------------------------------------------
// Launch
// ---------------------------------------------------------------------------
extern "C" void kernel_launch(void* const* d_in, const int* in_sizes, int n_in,
                              void* d_out, int out_size)
{
    const float* X   = (const float*)d_in[0];
    const float* rot = (const float*)d_in[1];
    const float* W[4]  = {(const float*)d_in[2], (const float*)d_in[4],
                          (const float*)d_in[6], (const float*)d_in[8]};
    const float* Bv[4] = {(const float*)d_in[3], (const float*)d_in[5],
                          (const float*)d_in[7], (const float*)d_in[9]};
    float* out = (float*)d_out;

    float *Qp, *Kp, *Vp, *AOp;
    __nv_bfloat16 *Xhi, *Xlo, *AOhi, *AOlo, *Whi, *Wlo;
    cudaGetSymbolAddress((void**)&Qp,   g_Q);
    cudaGetSymbolAddress((void**)&Kp,   g_K);
    cudaGetSymbolAddress((void**)&Vp,   g_V);
    cudaGetSymbolAddress((void**)&AOp,  g_AO);
    cudaGetSymbolAddress((void**)&Xhi,  g_Xhi);
    cudaGetSymbolAddress((void**)&Xlo,  g_Xlo);
    cudaGetSymbolAddress((void**)&AOhi, g_AOhi);
    cudaGetSymbolAddress((void**)&AOlo, g_AOlo);
    cudaGetSymbolAddress((void**)&Whi,  g_Whi);
    cudaGetSymbolAddress((void**)&Wlo,  g_Wlo);

    cudaFuncSetAttribute(gemm_hmma_kernel,
                         cudaFuncAttributeMaxDynamicSharedMemorySize, GEMM_SMEM);
    const int ATTN_SMEM = (BQ * PAD + BKV * PAD + BKV * PAD + BQ * PAD) * 4;
    cudaFuncSetAttribute(attn_kernel,
                         cudaFuncAttributeMaxDynamicSharedMemorySize, ATTN_SMEM);

    // Weight transpose+split (w -> [N][K] bf16 hi/lo)
    for (int i = 0; i < 4; i++)
        transpose_split_kernel<<<dim3(32, 32), dim3(32, 32)>>>(
            W[i], Whi + (size_t)i * EE * EE, Wlo + (size_t)i * EE * EE);

    // Activation split
    split_convert_kernel<<<(MM * EE / 4 + 255) / 256, 256>>>(X, Xhi, Xlo, MM * EE / 4);

    dim3 gemm_grid(EE / 128, MM / 128);   // (8, 64)
    gemm_hmma_kernel<<<gemm_grid, 256, GEMM_SMEM>>>(
        Xhi, Xlo, Whi + 0 * (size_t)EE * EE, Wlo + 0 * (size_t)EE * EE, Bv[0], Qp);
    gemm_hmma_kernel<<<gemm_grid, 256, GEMM_SMEM>>>(
        Xhi, Xlo, Whi + 1 * (size_t)EE * EE, Wlo + 1 * (size_t)EE * EE, Bv[1], Kp);
    gemm_hmma_kernel<<<gemm_grid, 256, GEMM_SMEM>>>(
        Xhi, Xlo, Whi + 2 * (size_t)EE * EE, Wlo + 2 * (size_t)EE * EE, Bv[2], Vp);

    int rope_total = BB * SS * HH * 32;
    rope_kernel<<<(rope_total + 255) / 256, 256>>>(Qp, Kp, rot);

    attn_kernel<<<dim3(SS / BQ, BB * HH), 256, ATTN_SMEM>>>(Qp, Kp, Vp, AOp);

    split_convert_kernel<<<(MM * EE / 4 + 255) / 256, 256>>>(AOp, AOhi, AOlo, MM * EE / 4);

    gemm_hmma_kernel<<<gemm_grid, 256, GEMM_SMEM>>>(
        AOhi, AOlo, Whi + 3 * (size_t)EE * EE, Wlo + 3 * (size_t)EE * EE, Bv[3], out);
}

// round 5
// speedup vs baseline: 2.1078x; 1.4758x over previous
#include <cuda_runtime.h>
#include <cuda_bf16.h>
#include <math_constants.h>
#include <cstdint>

// Problem constants
#define BB 8
#define SS 1024
#define EE 1024
#define HH 16
#define DD 64
#define MM (BB * SS)   // 8192

// ---------------------------------------------------------------------------
// Scratch (device globals — no allocation allowed)
// ---------------------------------------------------------------------------
__device__ float g_Q[MM * EE];
__device__ float g_K[MM * EE];
__device__ float g_V[MM * EE];
__device__ float g_AO[MM * EE];
__device__ __nv_bfloat16 g_Xhi[MM * EE];
__device__ __nv_bfloat16 g_Xlo[MM * EE];
__device__ __nv_bfloat16 g_AOhi[MM * EE];
__device__ __nv_bfloat16 g_AOlo[MM * EE];
// Attention operands, head-major [b][h][s][d], bf16 hi/lo
__device__ __nv_bfloat16 g_aQh[MM * EE];
__device__ __nv_bfloat16 g_aQl[MM * EE];
__device__ __nv_bfloat16 g_aKh[MM * EE];
__device__ __nv_bfloat16 g_aKl[MM * EE];
__device__ __nv_bfloat16 g_aVh[MM * EE];
__device__ __nv_bfloat16 g_aVl[MM * EE];
// Transposed weights: [N][K] bf16, hi/lo split. Index: 0=q,1=k,2=v,3=o
__device__ __nv_bfloat16 g_Whi[4][EE * EE];
__device__ __nv_bfloat16 g_Wlo[4][EE * EE];

// ---------------------------------------------------------------------------
// Helpers
// ---------------------------------------------------------------------------
__device__ __forceinline__ uint32_t smem_u32(const void* p) {
    uint32_t a;
    asm("{ .reg .u64 t; cvta.to.shared.u64 t, %1; cvt.u32.u64 %0, t; }"
        : "=r"(a) : "l"(p));
    return a;
}

__device__ __forceinline__ void ldsm_x4(uint32_t* r, uint32_t addr) {
    asm volatile("ldmatrix.sync.aligned.m8n8.x4.shared.b16 {%0,%1,%2,%3}, [%4];"
                 : "=r"(r[0]), "=r"(r[1]), "=r"(r[2]), "=r"(r[3]) : "r"(addr));
}

__device__ __forceinline__ void ldsm_x4_t(uint32_t* r, uint32_t addr) {
    asm volatile("ldmatrix.sync.aligned.m8n8.x4.trans.shared.b16 {%0,%1,%2,%3}, [%4];"
                 : "=r"(r[0]), "=r"(r[1]), "=r"(r[2]), "=r"(r[3]) : "r"(addr));
}

__device__ __forceinline__ void mma_bf16(float* d, const uint32_t* a,
                                         uint32_t b0, uint32_t b1) {
    asm volatile(
        "mma.sync.aligned.m16n8k16.row.col.f32.bf16.bf16.f32 "
        "{%0,%1,%2,%3}, {%4,%5,%6,%7}, {%8,%9}, {%0,%1,%2,%3};"
        : "+f"(d[0]), "+f"(d[1]), "+f"(d[2]), "+f"(d[3])
        : "r"(a[0]), "r"(a[1]), "r"(a[2]), "r"(a[3]), "r"(b0), "r"(b1));
}

// Split two floats into packed bf16 hi pair + lo pair
__device__ __forceinline__ void pack_hilo(float x, float y,
                                          uint32_t& h, uint32_t& l) {
    __nv_bfloat162 hv = __floats2bfloat162_rn(x, y);
    float hx = __bfloat162float(hv.x), hy = __bfloat162float(hv.y);
    __nv_bfloat162 lv = __floats2bfloat162_rn(x - hx, y - hy);
    h = reinterpret_cast<uint32_t&>(hv);
    l = reinterpret_cast<uint32_t&>(lv);
}

#define CP_ASYNC16(dst, src) \
    asm volatile("cp.async.cg.shared.global [%0], [%1], 16;\n" \
                 :: "r"(dst), "l"(src) : "memory")
#define CP_COMMIT() asm volatile("cp.async.commit_group;\n" ::: "memory")

// ---------------------------------------------------------------------------
// fp32 -> bf16 hi/lo split (no transpose)
// ---------------------------------------------------------------------------
__global__ void split_convert_kernel(const float* __restrict__ X,
                                     __nv_bfloat16* __restrict__ hi,
                                     __nv_bfloat16* __restrict__ lo, int n4)
{
    int i = blockIdx.x * blockDim.x + threadIdx.x;
    if (i >= n4) return;
    float4 v = *(const float4*)&X[i * 4];
    float vv[4] = {v.x, v.y, v.z, v.w};
    #pragma unroll
    for (int j = 0; j < 4; j++) {
        __nv_bfloat16 h = __float2bfloat16(vv[j]);
        float r = vv[j] - __bfloat162float(h);
        hi[i * 4 + j] = h;
        lo[i * 4 + j] = __float2bfloat16(r);
    }
}

// ---------------------------------------------------------------------------
// Weight transpose + split: W[K][N] fp32 -> Wt[N][K] bf16 hi/lo
// ---------------------------------------------------------------------------
__global__ __launch_bounds__(1024) void transpose_split_kernel(
    const float* __restrict__ W,
    __nv_bfloat16* __restrict__ Whi, __nv_bfloat16* __restrict__ Wlo)
{
    __shared__ float t[32][33];
    int k = blockIdx.y * 32 + threadIdx.y;
    int n = blockIdx.x * 32 + threadIdx.x;
    t[threadIdx.y][threadIdx.x] = W[(size_t)k * EE + n];
    __syncthreads();
    int nn = blockIdx.x * 32 + threadIdx.y;
    int kk = blockIdx.y * 32 + threadIdx.x;
    float v = t[threadIdx.x][threadIdx.y];
    __nv_bfloat16 h = __float2bfloat16(v);
    float r = v - __bfloat162float(h);
    Whi[(size_t)nn * EE + kk] = h;
    Wlo[(size_t)nn * EE + kk] = __float2bfloat16(r);
}

// ---------------------------------------------------------------------------
// HMMA bf16 3-pass split GEMM (unchanged from round 3)
// ---------------------------------------------------------------------------
#define BKG 32
#define NIT (EE / BKG)          // 32
#define ROWB 80
#define MATB (128 * ROWB)
#define OAH 0
#define OAL (1 * MATB)
#define OBH (2 * MATB)
#define OBL (3 * MATB)
#define STGB (4 * MATB)
#define GSTAGES 3
#define GEMM_SMEM (GSTAGES * STGB)  // 122880 B

__global__ __launch_bounds__(256) void gemm_hmma_kernel(
    const __nv_bfloat16* __restrict__ Ahi, const __nv_bfloat16* __restrict__ Alo,
    const __nv_bfloat16* __restrict__ Bhi, const __nv_bfloat16* __restrict__ Blo,
    const float* __restrict__ bias, float* __restrict__ C)
{
    extern __shared__ char smraw[];
    const uint32_t sb = smem_u32(smraw);
    const int tid  = threadIdx.x;
    const int wid  = tid >> 5;
    const int lane = tid & 31;
    const int m0 = blockIdx.y * 128;
    const int n0 = blockIdx.x * 128;
    const int wm = (wid & 1) * 64;
    const int wn = (wid >> 1) * 32;

    const int lr = tid >> 2;
    const int lc = tid & 3;
    const __nv_bfloat16* gsrc[4] = {
        Ahi + (size_t)(m0 + lr) * EE + lc * 8,
        Alo + (size_t)(m0 + lr) * EE + lc * 8,
        Bhi + (size_t)(n0 + lr) * EE + lc * 8,
        Blo + (size_t)(n0 + lr) * EE + lc * 8
    };
    const uint32_t dst0 = sb + lr * ROWB + lc * 16;

    const uint32_t a_off = (wm + (lane & 15)) * ROWB + (lane >> 4) * 16;
    const uint32_t b_off = (wn + ((lane >> 4) << 3) + (lane & 7)) * ROWB
                         + ((lane >> 3) & 1) * 16;

    float d[4][4][4];
    #pragma unroll
    for (int mt = 0; mt < 4; mt++)
        #pragma unroll
        for (int nt = 0; nt < 4; nt++)
            #pragma unroll
            for (int i = 0; i < 4; i++) d[mt][nt][i] = 0.f;

    #pragma unroll
    for (int s = 0; s < 2; s++) {
        #pragma unroll
        for (int mat = 0; mat < 4; mat++) {
            #pragma unroll
            for (int p = 0; p < 2; p++) {
                uint32_t dst = dst0 + s * STGB + mat * MATB + p * 64 * ROWB;
                const void* g = gsrc[mat] + (size_t)p * 64 * EE + s * BKG;
                CP_ASYNC16(dst, g);
            }
        }
        CP_COMMIT();
    }

    for (int it = 0; it < NIT; it++) {
        if (it < NIT - 2)
            asm volatile("cp.async.wait_group 1;\n" ::: "memory");
        else
            asm volatile("cp.async.wait_group 0;\n" ::: "memory");
        __syncthreads();

        if (it + 2 < NIT) {
            int s = (it + 2) % GSTAGES;
            int k0 = (it + 2) * BKG;
            #pragma unroll
            for (int mat = 0; mat < 4; mat++) {
                #pragma unroll
                for (int p = 0; p < 2; p++) {
                    uint32_t dst = dst0 + s * STGB + mat * MATB + p * 64 * ROWB;
                    const void* g = gsrc[mat] + (size_t)p * 64 * EE + k0;
                    CP_ASYNC16(dst, g);
                }
            }
            CP_COMMIT();
        }

        const uint32_t st = sb + (it % GSTAGES) * STGB;
        #pragma unroll
        for (int kc = 0; kc < 2; kc++) {
            uint32_t ah[4][4], al[4][4], bh[2][4], bl[2][4];
            #pragma unroll
            for (int mt = 0; mt < 4; mt++) {
                ldsm_x4(ah[mt], st + OAH + a_off + mt * 16 * ROWB + kc * 32);
                ldsm_x4(al[mt], st + OAL + a_off + mt * 16 * ROWB + kc * 32);
            }
            #pragma unroll
            for (int np = 0; np < 2; np++) {
                ldsm_x4(bh[np], st + OBH + b_off + np * 16 * ROWB + kc * 32);
                ldsm_x4(bl[np], st + OBL + b_off + np * 16 * ROWB + kc * 32);
            }
            #pragma unroll
            for (int mt = 0; mt < 4; mt++) {
                #pragma unroll
                for (int nt = 0; nt < 4; nt++) {
                    int np = nt >> 1, sc = (nt & 1) * 2;
                    mma_bf16(d[mt][nt], ah[mt], bh[np][sc], bh[np][sc + 1]);
                    mma_bf16(d[mt][nt], ah[mt], bl[np][sc], bl[np][sc + 1]);
                    mma_bf16(d[mt][nt], al[mt], bh[np][sc], bh[np][sc + 1]);
                }
            }
        }
        __syncthreads();
    }

    #pragma unroll
    for (int mt = 0; mt < 4; mt++) {
        int r = m0 + wm + mt * 16 + (lane >> 2);
        #pragma unroll
        for (int nt = 0; nt < 4; nt++) {
            int c = n0 + wn + nt * 8 + (lane & 3) * 2;
            float2 bb = *(const float2*)&bias[c];
            float2 o0 = {d[mt][nt][0] + bb.x, d[mt][nt][1] + bb.y};
            float2 o1 = {d[mt][nt][2] + bb.x, d[mt][nt][3] + bb.y};
            *(float2*)&C[(size_t)r * EE + c] = o0;
            *(float2*)&C[(size_t)(r + 8) * EE + c] = o1;
        }
    }
}

// ---------------------------------------------------------------------------
// RoPE + hi/lo split, layout change [b,s,h,d] fp32 -> [b,h,s,d] bf16 x2
// ---------------------------------------------------------------------------
__global__ void rope_split_kernel(const float* __restrict__ Q,
                                  const float* __restrict__ K,
                                  const float* __restrict__ freqs,
                                  __nv_bfloat16* __restrict__ Qh,
                                  __nv_bfloat16* __restrict__ Ql,
                                  __nv_bfloat16* __restrict__ Kh,
                                  __nv_bfloat16* __restrict__ Kl)
{
    int idx = blockIdx.x * blockDim.x + threadIdx.x;
    if (idx >= BB * SS * HH * 32) return;
    int dh = idx & 31;
    int h  = (idx >> 5) & (HH - 1);
    int bs = idx >> 9;
    int s  = bs & (SS - 1);
    int b  = bs >> 10;

    float f = freqs[s * 32 + dh];
    float sf, cf;
    sincosf(f, &sf, &cf);

    size_t src = (size_t)bs * EE + h * DD + dh;
    size_t dst = ((size_t)(b * HH + h) * SS + s) * DD + dh;

    float q1 = Q[src], q2 = Q[src + 32];
    float k1 = K[src], k2 = K[src + 32];
    float qr1 = q1 * cf - q2 * sf, qr2 = q2 * cf + q1 * sf;
    float kr1 = k1 * cf - k2 * sf, kr2 = k2 * cf + k1 * sf;

    __nv_bfloat16 hv;
    hv = __float2bfloat16(qr1); Qh[dst] = hv;
    Ql[dst] = __float2bfloat16(qr1 - __bfloat162float(hv));
    hv = __float2bfloat16(qr2); Qh[dst + 32] = hv;
    Ql[dst + 32] = __float2bfloat16(qr2 - __bfloat162float(hv));
    hv = __float2bfloat16(kr1); Kh[dst] = hv;
    Kl[dst] = __float2bfloat16(kr1 - __bfloat162float(hv));
    hv = __float2bfloat16(kr2); Kh[dst + 32] = hv;
    Kl[dst + 32] = __float2bfloat16(kr2 - __bfloat162float(hv));
}

// ---------------------------------------------------------------------------
// V hi/lo split + layout change [b,s,h,d] fp32 -> [b,h,s,d] bf16 x2
// ---------------------------------------------------------------------------
__global__ void v_split_kernel(const float* __restrict__ V,
                               __nv_bfloat16* __restrict__ Vh,
                               __nv_bfloat16* __restrict__ Vl)
{
    int idx = blockIdx.x * blockDim.x + threadIdx.x;
    if (idx >= MM * EE / 4) return;
    int d4 = idx & 15;
    int h  = (idx >> 4) & (HH - 1);
    int bs = idx >> 8;
    int s  = bs & (SS - 1);
    int b  = bs >> 10;

    float4 v = *(const float4*)&V[(size_t)bs * EE + h * DD + d4 * 4];
    size_t dst = ((size_t)(b * HH + h) * SS + s) * DD + d4 * 4;
    float vv[4] = {v.x, v.y, v.z, v.w};
    #pragma unroll
    for (int j = 0; j < 4; j++) {
        __nv_bfloat16 hh = __float2bfloat16(vv[j]);
        Vh[dst + j] = hh;
        Vl[dst + j] = __float2bfloat16(vv[j] - __bfloat162float(hh));
    }
}

// ---------------------------------------------------------------------------
// HMMA FlashAttention-2, bf16 hi/lo 3-pass for QK^T and PV.
// Grid (S/128, B*H), 256 threads (8 warps x m16 rows). KV blocks of 64,
// double-buffered cp.async. Softmax + P entirely in registers.
// ---------------------------------------------------------------------------
#define ROWA 144
#define A_QTILE (128 * ROWA)     // 18432
#define A_KV (64 * ROWA)         // 9216
#define A_STG (4 * A_KV)         // 36864
#define ATTN_SMEM (2 * A_QTILE + 2 * A_STG)   // 110592

__global__ __launch_bounds__(256) void attn_hmma_kernel(
    const __nv_bfloat16* __restrict__ Qh, const __nv_bfloat16* __restrict__ Ql,
    const __nv_bfloat16* __restrict__ Kh, const __nv_bfloat16* __restrict__ Kl,
    const __nv_bfloat16* __restrict__ Vh, const __nv_bfloat16* __restrict__ Vl,
    float* __restrict__ AO)
{
    extern __shared__ char smraw[];
    const uint32_t sb = smem_u32(smraw);
    const int tid = threadIdx.x;
    const int wid = tid >> 5;
    const int lane = tid & 31;
    const int bh = blockIdx.y;
    const int b = bh >> 4, h = bh & (HH - 1);
    const int q0 = blockIdx.x * 128;

    const size_t hbase = (size_t)bh * SS * DD;
    const __nv_bfloat16* Qhp = Qh + hbase + (size_t)q0 * DD;
    const __nv_bfloat16* Qlp = Ql + hbase + (size_t)q0 * DD;
    const __nv_bfloat16* kv_src[4] = {Kh + hbase, Kl + hbase,
                                      Vh + hbase, Vl + hbase};

    const uint32_t sQh = sb, sQl = sb + A_QTILE;
    const uint32_t sKV = sb + 2 * A_QTILE;

    const int lr = tid >> 2;       // 0..63
    const int lc = tid & 3;        // chunk base

    // ---- Q tile loads (128 rows x 128B, hi+lo), group 0 with KV block 0
    #pragma unroll
    for (int p = 0; p < 2; p++) {
        int r = lr + p * 64;
        #pragma unroll
        for (int cc = 0; cc < 2; cc++) {
            int ch = lc + cc * 4;
            CP_ASYNC16(sQh + r * ROWA + ch * 16, Qhp + (size_t)r * DD + ch * 8);
            CP_ASYNC16(sQl + r * ROWA + ch * 16, Qlp + (size_t)r * DD + ch * 8);
        }
    }
    // KV block 0
    #pragma unroll
    for (int mat = 0; mat < 4; mat++) {
        #pragma unroll
        for (int cc = 0; cc < 2; cc++) {
            int ch = lc + cc * 4;
            CP_ASYNC16(sKV + mat * A_KV + lr * ROWA + ch * 16,
                       kv_src[mat] + (size_t)lr * DD + ch * 8);
        }
    }
    CP_COMMIT();
    // KV block 1
    #pragma unroll
    for (int mat = 0; mat < 4; mat++) {
        #pragma unroll
        for (int cc = 0; cc < 2; cc++) {
            int ch = lc + cc * 4;
            CP_ASYNC16(sKV + A_STG + mat * A_KV + lr * ROWA + ch * 16,
                       kv_src[mat] + (size_t)(64 + lr) * DD + ch * 8);
        }
    }
    CP_COMMIT();

    asm volatile("cp.async.wait_group 1;\n" ::: "memory");
    __syncthreads();

    // Preload Q fragments (constant over KV loop)
    const uint32_t a_off = (wid * 16 + (lane & 15)) * ROWA + (lane >> 4) * 16;
    uint32_t qh[4][4], ql[4][4];
    #pragma unroll
    for (int kk = 0; kk < 4; kk++) {
        ldsm_x4(qh[kk], sQh + a_off + kk * 32);
        ldsm_x4(ql[kk], sQl + a_off + kk * 32);
    }

    const uint32_t b_off = (((lane >> 4) << 3) + (lane & 7)) * ROWA
                         + ((lane >> 3) & 1) * 16;
    const uint32_t v_off = (lane & 15) * ROWA + (lane >> 4) * 16;

    float m0 = -CUDART_INF_F, m1 = -CUDART_INF_F, l0 = 0.f, l1 = 0.f;
    float o[8][4];
    #pragma unroll
    for (int j = 0; j < 8; j++)
        #pragma unroll
        for (int i = 0; i < 4; i++) o[j][i] = 0.f;

    const float scale = 0.125f;

    for (int it = 0; it < 16; it++) {
        if (it > 0) {
            if (it < 14)
                asm volatile("cp.async.wait_group 1;\n" ::: "memory");
            else
                asm volatile("cp.async.wait_group 0;\n" ::: "memory");
            __syncthreads();
        }
        const uint32_t st = sKV + (it & 1) * A_STG;

        // ---- S = Q K^T (3-pass)
        float s[8][4];
        #pragma unroll
        for (int j = 0; j < 8; j++)
            #pragma unroll
            for (int i = 0; i < 4; i++) s[j][i] = 0.f;

        #pragma unroll
        for (int np = 0; np < 4; np++) {
            #pragma unroll
            for (int kk = 0; kk < 4; kk++) {
                uint32_t kh4[4], kl4[4];
                ldsm_x4(kh4, st + 0 * A_KV + b_off + np * 16 * ROWA + kk * 32);
                ldsm_x4(kl4, st + 1 * A_KV + b_off + np * 16 * ROWA + kk * 32);
                mma_bf16(s[np * 2 + 0], qh[kk], kh4[0], kh4[1]);
                mma_bf16(s[np * 2 + 1], qh[kk], kh4[2], kh4[3]);
                mma_bf16(s[np * 2 + 0], qh[kk], kl4[0], kl4[1]);
                mma_bf16(s[np * 2 + 1], qh[kk], kl4[2], kl4[3]);
                mma_bf16(s[np * 2 + 0], ql[kk], kh4[0], kh4[1]);
                mma_bf16(s[np * 2 + 1], ql[kk], kh4[2], kh4[3]);
            }
        }

        // ---- online softmax (rows lane>>2 and +8)
        float rmax0 = -CUDART_INF_F, rmax1 = -CUDART_INF_F;
        #pragma unroll
        for (int j = 0; j < 8; j++) {
            #pragma unroll
            for (int i = 0; i < 4; i++) s[j][i] *= scale;
            rmax0 = fmaxf(rmax0, fmaxf(s[j][0], s[j][1]));
            rmax1 = fmaxf(rmax1, fmaxf(s[j][2], s[j][3]));
        }
        rmax0 = fmaxf(rmax0, __shfl_xor_sync(0xffffffffu, rmax0, 1));
        rmax0 = fmaxf(rmax0, __shfl_xor_sync(0xffffffffu, rmax0, 2));
        rmax1 = fmaxf(rmax1, __shfl_xor_sync(0xffffffffu, rmax1, 1));
        rmax1 = fmaxf(rmax1, __shfl_xor_sync(0xffffffffu, rmax1, 2));

        float mn0 = fmaxf(m0, rmax0), mn1 = fmaxf(m1, rmax1);
        float c0 = __expf(m0 - mn0), c1 = __expf(m1 - mn1);
        m0 = mn0; m1 = mn1;

        float rs0 = 0.f, rs1 = 0.f;
        #pragma unroll
        for (int j = 0; j < 8; j++) {
            s[j][0] = __expf(s[j][0] - mn0); rs0 += s[j][0];
            s[j][1] = __expf(s[j][1] - mn0); rs0 += s[j][1];
            s[j][2] = __expf(s[j][2] - mn1); rs1 += s[j][2];
            s[j][3] = __expf(s[j][3] - mn1); rs1 += s[j][3];
        }
        rs0 += __shfl_xor_sync(0xffffffffu, rs0, 1);
        rs0 += __shfl_xor_sync(0xffffffffu, rs0, 2);
        rs1 += __shfl_xor_sync(0xffffffffu, rs1, 1);
        rs1 += __shfl_xor_sync(0xffffffffu, rs1, 2);
        l0 = l0 * c0 + rs0;
        l1 = l1 * c1 + rs1;

        #pragma unroll
        for (int j = 0; j < 8; j++) {
            o[j][0] *= c0; o[j][1] *= c0;
            o[j][2] *= c1; o[j][3] *= c1;
        }

        // ---- O += P V (3-pass, P packed hi/lo in registers)
        #pragma unroll
        for (int kk = 0; kk < 4; kk++) {
            uint32_t ph[4], pl[4];
            pack_hilo(s[2 * kk][0],     s[2 * kk][1],     ph[0], pl[0]);
            pack_hilo(s[2 * kk][2],     s[2 * kk][3],     ph[1], pl[1]);
            pack_hilo(s[2 * kk + 1][0], s[2 * kk + 1][1], ph[2], pl[2]);
            pack_hilo(s[2 * kk + 1][2], s[2 * kk + 1][3], ph[3], pl[3]);
            #pragma unroll
            for (int np = 0; np < 4; np++) {
                uint32_t vh4[4], vl4[4];
                ldsm_x4_t(vh4, st + 2 * A_KV + v_off + kk * 16 * ROWA + np * 32);
                ldsm_x4_t(vl4, st + 3 * A_KV + v_off + kk * 16 * ROWA + np * 32);
                mma_bf16(o[np * 2 + 0], ph, vh4[0], vh4[1]);
                mma_bf16(o[np * 2 + 1], ph, vh4[2], vh4[3]);
                mma_bf16(o[np * 2 + 0], ph, vl4[0], vl4[1]);
                mma_bf16(o[np * 2 + 1], ph, vl4[2], vl4[3]);
                mma_bf16(o[np * 2 + 0], pl, vh4[0], vh4[1]);
                mma_bf16(o[np * 2 + 1], pl, vh4[2], vh4[3]);
            }
        }

        __syncthreads();
        if (it + 2 < 16) {
            uint32_t dstg = sKV + (it & 1) * A_STG;
            #pragma unroll
            for (int mat = 0; mat < 4; mat++) {
                #pragma unroll
                for (int cc = 0; cc < 2; cc++) {
                    int ch = lc + cc * 4;
                    CP_ASYNC16(dstg + mat * A_KV + lr * ROWA + ch * 16,
                               kv_src[mat] + (size_t)((it + 2) * 64 + lr) * DD + ch * 8);
                }
            }
            CP_COMMIT();
        }
    }

    // ---- epilogue: normalize + store to AO [b][s][h*64+d] fp32
    float inv0 = 1.f / l0, inv1 = 1.f / l1;
    int r0 = q0 + wid * 16 + (lane >> 2);
    float* row0 = AO + (size_t)(b * SS + r0) * EE + h * DD;
    float* row1 = row0 + (size_t)8 * EE;
    int c0l = (lane & 3) * 2;
    #pragma unroll
    for (int j = 0; j < 8; j++) {
        float2 w0 = {o[j][0] * inv0, o[j][1] * inv0};
        float2 w1 = {o[j][2] * inv1, o[j][3] * inv1};
        *(float2*)&row0[j * 8 + c0l] = w0;
        *(float2*)&row1[j * 8 + c0l] = w1;
    }
}

// ---------------------------------------------------------------------------
// Launch
// ---------------------------------------------------------------------------
extern "C" void kernel_launch(void* const* d_in, const int* in_sizes, int n_in,
                              void* d_out, int out_size)
{
    const float* X   = (const float*)d_in[0];
    const float* rot = (const float*)d_in[1];
    const float* W[4]  = {(const float*)d_in[2], (const float*)d_in[4],
                          (const float*)d_in[6], (const float*)d_in[8]};
    const float* Bv[4] = {(const float*)d_in[3], (const float*)d_in[5],
                          (const float*)d_in[7], (const float*)d_in[9]};
    float* out = (float*)d_out;

    float *Qp, *Kp, *Vp, *AOp;
    __nv_bfloat16 *Xhi, *Xlo, *AOhi, *AOlo, *Whi, *Wlo;
    __nv_bfloat16 *aQh, *aQl, *aKh, *aKl, *aVh, *aVl;
    cudaGetSymbolAddress((void**)&Qp,   g_Q);
    cudaGetSymbolAddress((void**)&Kp,   g_K);
    cudaGetSymbolAddress((void**)&Vp,   g_V);
    cudaGetSymbolAddress((void**)&AOp,  g_AO);
    cudaGetSymbolAddress((void**)&Xhi,  g_Xhi);
    cudaGetSymbolAddress((void**)&Xlo,  g_Xlo);
    cudaGetSymbolAddress((void**)&AOhi, g_AOhi);
    cudaGetSymbolAddress((void**)&AOlo, g_AOlo);
    cudaGetSymbolAddress((void**)&Whi,  g_Whi);
    cudaGetSymbolAddress((void**)&Wlo,  g_Wlo);
    cudaGetSymbolAddress((void**)&aQh,  g_aQh);
    cudaGetSymbolAddress((void**)&aQl,  g_aQl);
    cudaGetSymbolAddress((void**)&aKh,  g_aKh);
    cudaGetSymbolAddress((void**)&aKl,  g_aKl);
    cudaGetSymbolAddress((void**)&aVh,  g_aVh);
    cudaGetSymbolAddress((void**)&aVl,  g_aVl);

    cudaFuncSetAttribute(gemm_hmma_kernel,
                         cudaFuncAttributeMaxDynamicSharedMemorySize, GEMM_SMEM);
    cudaFuncSetAttribute(attn_hmma_kernel,
                         cudaFuncAttributeMaxDynamicSharedMemorySize, ATTN_SMEM);

    for (int i = 0; i < 4; i++)
        transpose_split_kernel<<<dim3(32, 32), dim3(32, 32)>>>(
            W[i], Whi + (size_t)i * EE * EE, Wlo + (size_t)i * EE * EE);

    split_convert_kernel<<<(MM * EE / 4 + 255) / 256, 256>>>(X, Xhi, Xlo, MM * EE / 4);

    dim3 gemm_grid(EE / 128, MM / 128);
    gemm_hmma_kernel<<<gemm_grid, 256, GEMM_SMEM>>>(
        Xhi, Xlo, Whi + 0 * (size_t)EE * EE, Wlo + 0 * (size_t)EE * EE, Bv[0], Qp);
    gemm_hmma_kernel<<<gemm_grid, 256, GEMM_SMEM>>>(
        Xhi, Xlo, Whi + 1 * (size_t)EE * EE, Wlo + 1 * (size_t)EE * EE, Bv[1], Kp);
    gemm_hmma_kernel<<<gemm_grid, 256, GEMM_SMEM>>>(
        Xhi, Xlo, Whi + 2 * (size_t)EE * EE, Wlo + 2 * (size_t)EE * EE, Bv[2], Vp);

    int rope_total = BB * SS * HH * 32;
    rope_split_kernel<<<(rope_total + 255) / 256, 256>>>(
        Qp, Kp, rot, aQh, aQl, aKh, aKl);
    v_split_kernel<<<(MM * EE / 4 + 255) / 256, 256>>>(Vp, aVh, aVl);

    attn_hmma_kernel<<<dim3(SS / 128, BB * HH), 256, ATTN_SMEM>>>(
        aQh, aQl, aKh, aKl, aVh, aVl, AOp);

    split_convert_kernel<<<(MM * EE / 4 + 255) / 256, 256>>>(AOp, AOhi, AOlo, MM * EE / 4);

    gemm_hmma_kernel<<<gemm_grid, 256, GEMM_SMEM>>>(
        AOhi, AOlo, Whi + 3 * (size_t)EE * EE, Wlo + 3 * (size_t)EE * EE, Bv[3], out);
}

// round 6
// speedup vs baseline: 2.1086x; 1.0004x over previous
#include <cuda_runtime.h>
#include <cuda_bf16.h>
#include <math_constants.h>
#include <cstdint>

// Problem constants
#define BB 8
#define SS 1024
#define EE 1024
#define HH 16
#define DD 64
#define MM (BB * SS)   // 8192

// ---------------------------------------------------------------------------
// Scratch (device globals — no allocation allowed)
// ---------------------------------------------------------------------------
__device__ float g_Q[MM * EE];
__device__ float g_K[MM * EE];
__device__ float g_V[MM * EE];
__device__ float g_AO[MM * EE];
__device__ __nv_bfloat16 g_Xhi[MM * EE];
__device__ __nv_bfloat16 g_Xlo[MM * EE];
__device__ __nv_bfloat16 g_AOhi[MM * EE];
__device__ __nv_bfloat16 g_AOlo[MM * EE];
// Attention operands, head-major [b][h][s][d], bf16 hi/lo
__device__ __nv_bfloat16 g_aQh[MM * EE];
__device__ __nv_bfloat16 g_aQl[MM * EE];
__device__ __nv_bfloat16 g_aKh[MM * EE];
__device__ __nv_bfloat16 g_aKl[MM * EE];
__device__ __nv_bfloat16 g_aVh[MM * EE];
__device__ __nv_bfloat16 g_aVl[MM * EE];
// Transposed weights: [N][K] bf16, hi/lo split. Index: 0=q,1=k,2=v,3=o
__device__ __nv_bfloat16 g_Whi[4][EE * EE];
__device__ __nv_bfloat16 g_Wlo[4][EE * EE];

// ---------------------------------------------------------------------------
// Helpers
// ---------------------------------------------------------------------------
__device__ __forceinline__ uint32_t smem_u32(const void* p) {
    uint32_t a;
    asm("{ .reg .u64 t; cvta.to.shared.u64 t, %1; cvt.u32.u64 %0, t; }"
        : "=r"(a) : "l"(p));
    return a;
}

__device__ __forceinline__ void ldsm_x4(uint32_t* r, uint32_t addr) {
    asm volatile("ldmatrix.sync.aligned.m8n8.x4.shared.b16 {%0,%1,%2,%3}, [%4];"
                 : "=r"(r[0]), "=r"(r[1]), "=r"(r[2]), "=r"(r[3]) : "r"(addr));
}

__device__ __forceinline__ void ldsm_x4_t(uint32_t* r, uint32_t addr) {
    asm volatile("ldmatrix.sync.aligned.m8n8.x4.trans.shared.b16 {%0,%1,%2,%3}, [%4];"
                 : "=r"(r[0]), "=r"(r[1]), "=r"(r[2]), "=r"(r[3]) : "r"(addr));
}

__device__ __forceinline__ void mma_bf16(float* d, const uint32_t* a,
                                         uint32_t b0, uint32_t b1) {
    asm volatile(
        "mma.sync.aligned.m16n8k16.row.col.f32.bf16.bf16.f32 "
        "{%0,%1,%2,%3}, {%4,%5,%6,%7}, {%8,%9}, {%0,%1,%2,%3};"
        : "+f"(d[0]), "+f"(d[1]), "+f"(d[2]), "+f"(d[3])
        : "r"(a[0]), "r"(a[1]), "r"(a[2]), "r"(a[3]), "r"(b0), "r"(b1));
}

// Split two floats into packed bf16 hi pair + lo pair
__device__ __forceinline__ void pack_hilo(float x, float y,
                                          uint32_t& h, uint32_t& l) {
    __nv_bfloat162 hv = __floats2bfloat162_rn(x, y);
    float hx = __bfloat162float(hv.x), hy = __bfloat162float(hv.y);
    __nv_bfloat162 lv = __floats2bfloat162_rn(x - hx, y - hy);
    h = reinterpret_cast<uint32_t&>(hv);
    l = reinterpret_cast<uint32_t&>(lv);
}

#define CP_ASYNC16(dst, src) \
    asm volatile("cp.async.cg.shared.global [%0], [%1], 16;\n" \
                 :: "r"(dst), "l"(src) : "memory")
#define CP_COMMIT() asm volatile("cp.async.commit_group;\n" ::: "memory")

// ---------------------------------------------------------------------------
// fp32 -> bf16 hi/lo split (no transpose)
// ---------------------------------------------------------------------------
__global__ void split_convert_kernel(const float* __restrict__ X,
                                     __nv_bfloat16* __restrict__ hi,
                                     __nv_bfloat16* __restrict__ lo, int n4)
{
    int i = blockIdx.x * blockDim.x + threadIdx.x;
    if (i >= n4) return;
    float4 v = *(const float4*)&X[i * 4];
    float vv[4] = {v.x, v.y, v.z, v.w};
    #pragma unroll
    for (int j = 0; j < 4; j++) {
        __nv_bfloat16 h = __float2bfloat16(vv[j]);
        float r = vv[j] - __bfloat162float(h);
        hi[i * 4 + j] = h;
        lo[i * 4 + j] = __float2bfloat16(r);
    }
}

// ---------------------------------------------------------------------------
// Weight transpose + split: W[K][N] fp32 -> Wt[N][K] bf16 hi/lo
// ---------------------------------------------------------------------------
__global__ __launch_bounds__(1024) void transpose_split_kernel(
    const float* __restrict__ W,
    __nv_bfloat16* __restrict__ Whi, __nv_bfloat16* __restrict__ Wlo)
{
    __shared__ float t[32][33];
    int k = blockIdx.y * 32 + threadIdx.y;
    int n = blockIdx.x * 32 + threadIdx.x;
    t[threadIdx.y][threadIdx.x] = W[(size_t)k * EE + n];
    __syncthreads();
    int nn = blockIdx.x * 32 + threadIdx.y;
    int kk = blockIdx.y * 32 + threadIdx.x;
    float v = t[threadIdx.x][threadIdx.y];
    __nv_bfloat16 h = __float2bfloat16(v);
    float r = v - __bfloat162float(h);
    Whi[(size_t)nn * EE + kk] = h;
    Wlo[(size_t)nn * EE + kk] = __float2bfloat16(r);
}

// ---------------------------------------------------------------------------
// HMMA bf16 3-pass split GEMM (unchanged from round 3)
// ---------------------------------------------------------------------------
#define BKG 32
#define NIT (EE / BKG)          // 32
#define ROWB 80
#define MATB (128 * ROWB)
#define OAH 0
#define OAL (1 * MATB)
#define OBH (2 * MATB)
#define OBL (3 * MATB)
#define STGB (4 * MATB)
#define GSTAGES 3
#define GEMM_SMEM (GSTAGES * STGB)  // 122880 B

__global__ __launch_bounds__(256) void gemm_hmma_kernel(
    const __nv_bfloat16* __restrict__ Ahi, const __nv_bfloat16* __restrict__ Alo,
    const __nv_bfloat16* __restrict__ Bhi, const __nv_bfloat16* __restrict__ Blo,
    const float* __restrict__ bias, float* __restrict__ C)
{
    extern __shared__ char smraw[];
    const uint32_t sb = smem_u32(smraw);
    const int tid  = threadIdx.x;
    const int wid  = tid >> 5;
    const int lane = tid & 31;
    const int m0 = blockIdx.y * 128;
    const int n0 = blockIdx.x * 128;
    const int wm = (wid & 1) * 64;
    const int wn = (wid >> 1) * 32;

    const int lr = tid >> 2;
    const int lc = tid & 3;
    const __nv_bfloat16* gsrc[4] = {
        Ahi + (size_t)(m0 + lr) * EE + lc * 8,
        Alo + (size_t)(m0 + lr) * EE + lc * 8,
        Bhi + (size_t)(n0 + lr) * EE + lc * 8,
        Blo + (size_t)(n0 + lr) * EE + lc * 8
    };
    const uint32_t dst0 = sb + lr * ROWB + lc * 16;

    const uint32_t a_off = (wm + (lane & 15)) * ROWB + (lane >> 4) * 16;
    const uint32_t b_off = (wn + ((lane >> 4) << 3) + (lane & 7)) * ROWB
                         + ((lane >> 3) & 1) * 16;

    float d[4][4][4];
    #pragma unroll
    for (int mt = 0; mt < 4; mt++)
        #pragma unroll
        for (int nt = 0; nt < 4; nt++)
            #pragma unroll
            for (int i = 0; i < 4; i++) d[mt][nt][i] = 0.f;

    #pragma unroll
    for (int s = 0; s < 2; s++) {
        #pragma unroll
        for (int mat = 0; mat < 4; mat++) {
            #pragma unroll
            for (int p = 0; p < 2; p++) {
                uint32_t dst = dst0 + s * STGB + mat * MATB + p * 64 * ROWB;
                const void* g = gsrc[mat] + (size_t)p * 64 * EE + s * BKG;
                CP_ASYNC16(dst, g);
            }
        }
        CP_COMMIT();
    }

    for (int it = 0; it < NIT; it++) {
        if (it < NIT - 2)
            asm volatile("cp.async.wait_group 1;\n" ::: "memory");
        else
            asm volatile("cp.async.wait_group 0;\n" ::: "memory");
        __syncthreads();

        if (it + 2 < NIT) {
            int s = (it + 2) % GSTAGES;
            int k0 = (it + 2) * BKG;
            #pragma unroll
            for (int mat = 0; mat < 4; mat++) {
                #pragma unroll
                for (int p = 0; p < 2; p++) {
                    uint32_t dst = dst0 + s * STGB + mat * MATB + p * 64 * ROWB;
                    const void* g = gsrc[mat] + (size_t)p * 64 * EE + k0;
                    CP_ASYNC16(dst, g);
                }
            }
            CP_COMMIT();
        }

        const uint32_t st = sb + (it % GSTAGES) * STGB;
        #pragma unroll
        for (int kc = 0; kc < 2; kc++) {
            uint32_t ah[4][4], al[4][4], bh[2][4], bl[2][4];
            #pragma unroll
            for (int mt = 0; mt < 4; mt++) {
                ldsm_x4(ah[mt], st + OAH + a_off + mt * 16 * ROWB + kc * 32);
                ldsm_x4(al[mt], st + OAL + a_off + mt * 16 * ROWB + kc * 32);
            }
            #pragma unroll
            for (int np = 0; np < 2; np++) {
                ldsm_x4(bh[np], st + OBH + b_off + np * 16 * ROWB + kc * 32);
                ldsm_x4(bl[np], st + OBL + b_off + np * 16 * ROWB + kc * 32);
            }
            #pragma unroll
            for (int mt = 0; mt < 4; mt++) {
                #pragma unroll
                for (int nt = 0; nt < 4; nt++) {
                    int np = nt >> 1, sc = (nt & 1) * 2;
                    mma_bf16(d[mt][nt], ah[mt], bh[np][sc], bh[np][sc + 1]);
                    mma_bf16(d[mt][nt], ah[mt], bl[np][sc], bl[np][sc + 1]);
                    mma_bf16(d[mt][nt], al[mt], bh[np][sc], bh[np][sc + 1]);
                }
            }
        }
        __syncthreads();
    }

    #pragma unroll
    for (int mt = 0; mt < 4; mt++) {
        int r = m0 + wm + mt * 16 + (lane >> 2);
        #pragma unroll
        for (int nt = 0; nt < 4; nt++) {
            int c = n0 + wn + nt * 8 + (lane & 3) * 2;
            float2 bb = *(const float2*)&bias[c];
            float2 o0 = {d[mt][nt][0] + bb.x, d[mt][nt][1] + bb.y};
            float2 o1 = {d[mt][nt][2] + bb.x, d[mt][nt][3] + bb.y};
            *(float2*)&C[(size_t)r * EE + c] = o0;
            *(float2*)&C[(size_t)(r + 8) * EE + c] = o1;
        }
    }
}

// ---------------------------------------------------------------------------
// RoPE + hi/lo split, layout change [b,s,h,d] fp32 -> [b,h,s,d] bf16 x2
// ---------------------------------------------------------------------------
__global__ void rope_split_kernel(const float* __restrict__ Q,
                                  const float* __restrict__ K,
                                  const float* __restrict__ freqs,
                                  __nv_bfloat16* __restrict__ Qh,
                                  __nv_bfloat16* __restrict__ Ql,
                                  __nv_bfloat16* __restrict__ Kh,
                                  __nv_bfloat16* __restrict__ Kl)
{
    int idx = blockIdx.x * blockDim.x + threadIdx.x;
    if (idx >= BB * SS * HH * 32) return;
    int dh = idx & 31;
    int h  = (idx >> 5) & (HH - 1);
    int bs = idx >> 9;
    int s  = bs & (SS - 1);
    int b  = bs >> 10;

    float f = freqs[s * 32 + dh];
    float sf, cf;
    sincosf(f, &sf, &cf);

    size_t src = (size_t)bs * EE + h * DD + dh;
    size_t dst = ((size_t)(b * HH + h) * SS + s) * DD + dh;

    float q1 = Q[src], q2 = Q[src + 32];
    float k1 = K[src], k2 = K[src + 32];
    float qr1 = q1 * cf - q2 * sf, qr2 = q2 * cf + q1 * sf;
    float kr1 = k1 * cf - k2 * sf, kr2 = k2 * cf + k1 * sf;

    __nv_bfloat16 hv;
    hv = __float2bfloat16(qr1); Qh[dst] = hv;
    Ql[dst] = __float2bfloat16(qr1 - __bfloat162float(hv));
    hv = __float2bfloat16(qr2); Qh[dst + 32] = hv;
    Ql[dst + 32] = __float2bfloat16(qr2 - __bfloat162float(hv));
    hv = __float2bfloat16(kr1); Kh[dst] = hv;
    Kl[dst] = __float2bfloat16(kr1 - __bfloat162float(hv));
    hv = __float2bfloat16(kr2); Kh[dst + 32] = hv;
    Kl[dst + 32] = __float2bfloat16(kr2 - __bfloat162float(hv));
}

// ---------------------------------------------------------------------------
// V hi/lo split + layout change [b,s,h,d] fp32 -> [b,h,s,d] bf16 x2
// ---------------------------------------------------------------------------
__global__ void v_split_kernel(const float* __restrict__ V,
                               __nv_bfloat16* __restrict__ Vh,
                               __nv_bfloat16* __restrict__ Vl)
{
    int idx = blockIdx.x * blockDim.x + threadIdx.x;
    if (idx >= MM * EE / 4) return;
    int d4 = idx & 15;
    int h  = (idx >> 4) & (HH - 1);
    int bs = idx >> 8;
    int s  = bs & (SS - 1);
    int b  = bs >> 10;

    float4 v = *(const float4*)&V[(size_t)bs * EE + h * DD + d4 * 4];
    size_t dst = ((size_t)(b * HH + h) * SS + s) * DD + d4 * 4;
    float vv[4] = {v.x, v.y, v.z, v.w};
    #pragma unroll
    for (int j = 0; j < 4; j++) {
        __nv_bfloat16 hh = __float2bfloat16(vv[j]);
        Vh[dst + j] = hh;
        Vl[dst + j] = __float2bfloat16(vv[j] - __bfloat162float(hh));
    }
}

// ---------------------------------------------------------------------------
// HMMA FlashAttention-2, bf16 hi/lo 3-pass for QK^T and PV.
// Grid (S/128, B*H), 256 threads (8 warps x m16 rows). KV blocks of 64,
// double-buffered cp.async. Softmax + P entirely in registers.
// ---------------------------------------------------------------------------
#define ROWA 144
#define A_QTILE (128 * ROWA)     // 18432
#define A_KV (64 * ROWA)         // 9216
#define A_STG (4 * A_KV)         // 36864
#define ATTN_SMEM (2 * A_QTILE + 2 * A_STG)   // 110592

__global__ __launch_bounds__(256) void attn_hmma_kernel(
    const __nv_bfloat16* __restrict__ Qh, const __nv_bfloat16* __restrict__ Ql,
    const __nv_bfloat16* __restrict__ Kh, const __nv_bfloat16* __restrict__ Kl,
    const __nv_bfloat16* __restrict__ Vh, const __nv_bfloat16* __restrict__ Vl,
    float* __restrict__ AO)
{
    extern __shared__ char smraw[];
    const uint32_t sb = smem_u32(smraw);
    const int tid = threadIdx.x;
    const int wid = tid >> 5;
    const int lane = tid & 31;
    const int bh = blockIdx.y;
    const int b = bh >> 4, h = bh & (HH - 1);
    const int q0 = blockIdx.x * 128;

    const size_t hbase = (size_t)bh * SS * DD;
    const __nv_bfloat16* Qhp = Qh + hbase + (size_t)q0 * DD;
    const __nv_bfloat16* Qlp = Ql + hbase + (size_t)q0 * DD;
    const __nv_bfloat16* kv_src[4] = {Kh + hbase, Kl + hbase,
                                      Vh + hbase, Vl + hbase};

    const uint32_t sQh = sb, sQl = sb + A_QTILE;
    const uint32_t sKV = sb + 2 * A_QTILE;

    const int lr = tid >> 2;       // 0..63
    const int lc = tid & 3;        // chunk base

    // ---- Q tile loads (128 rows x 128B, hi+lo), group 0 with KV block 0
    #pragma unroll
    for (int p = 0; p < 2; p++) {
        int r = lr + p * 64;
        #pragma unroll
        for (int cc = 0; cc < 2; cc++) {
            int ch = lc + cc * 4;
            CP_ASYNC16(sQh + r * ROWA + ch * 16, Qhp + (size_t)r * DD + ch * 8);
            CP_ASYNC16(sQl + r * ROWA + ch * 16, Qlp + (size_t)r * DD + ch * 8);
        }
    }
    // KV block 0
    #pragma unroll
    for (int mat = 0; mat < 4; mat++) {
        #pragma unroll
        for (int cc = 0; cc < 2; cc++) {
            int ch = lc + cc * 4;
            CP_ASYNC16(sKV + mat * A_KV + lr * ROWA + ch * 16,
                       kv_src[mat] + (size_t)lr * DD + ch * 8);
        }
    }
    CP_COMMIT();
    // KV block 1
    #pragma unroll
    for (int mat = 0; mat < 4; mat++) {
        #pragma unroll
        for (int cc = 0; cc < 2; cc++) {
            int ch = lc + cc * 4;
            CP_ASYNC16(sKV + A_STG + mat * A_KV + lr * ROWA + ch * 16,
                       kv_src[mat] + (size_t)(64 + lr) * DD + ch * 8);
        }
    }
    CP_COMMIT();

    asm volatile("cp.async.wait_group 1;\n" ::: "memory");
    __syncthreads();

    // Preload Q fragments (constant over KV loop)
    const uint32_t a_off = (wid * 16 + (lane & 15)) * ROWA + (lane >> 4) * 16;
    uint32_t qh[4][4], ql[4][4];
    #pragma unroll
    for (int kk = 0; kk < 4; kk++) {
        ldsm_x4(qh[kk], sQh + a_off + kk * 32);
        ldsm_x4(ql[kk], sQl + a_off + kk * 32);
    }

    const uint32_t b_off = (((lane >> 4) << 3) + (lane & 7)) * ROWA
                         + ((lane >> 3) & 1) * 16;
    const uint32_t v_off = (lane & 15) * ROWA + (lane >> 4) * 16;

    float m0 = -CUDART_INF_F, m1 = -CUDART_INF_F, l0 = 0.f, l1 = 0.f;
    float o[8][4];
    #pragma unroll
    for (int j = 0; j < 8; j++)
        #pragma unroll
        for (int i = 0; i < 4; i++) o[j][i] = 0.f;

    const float scale = 0.125f;

    for (int it = 0; it < 16; it++) {
        if (it > 0) {
            if (it < 14)
                asm volatile("cp.async.wait_group 1;\n" ::: "memory");
            else
                asm volatile("cp.async.wait_group 0;\n" ::: "memory");
            __syncthreads();
        }
        const uint32_t st = sKV + (it & 1) * A_STG;

        // ---- S = Q K^T (3-pass)
        float s[8][4];
        #pragma unroll
        for (int j = 0; j < 8; j++)
            #pragma unroll
            for (int i = 0; i < 4; i++) s[j][i] = 0.f;

        #pragma unroll
        for (int np = 0; np < 4; np++) {
            #pragma unroll
            for (int kk = 0; kk < 4; kk++) {
                uint32_t kh4[4], kl4[4];
                ldsm_x4(kh4, st + 0 * A_KV + b_off + np * 16 * ROWA + kk * 32);
                ldsm_x4(kl4, st + 1 * A_KV + b_off + np * 16 * ROWA + kk * 32);
                mma_bf16(s[np * 2 + 0], qh[kk], kh4[0], kh4[1]);
                mma_bf16(s[np * 2 + 1], qh[kk], kh4[2], kh4[3]);
                mma_bf16(s[np * 2 + 0], qh[kk], kl4[0], kl4[1]);
                mma_bf16(s[np * 2 + 1], qh[kk], kl4[2], kl4[3]);
                mma_bf16(s[np * 2 + 0], ql[kk], kh4[0], kh4[1]);
                mma_bf16(s[np * 2 + 1], ql[kk], kh4[2], kh4[3]);
            }
        }

        // ---- online softmax (rows lane>>2 and +8)
        float rmax0 = -CUDART_INF_F, rmax1 = -CUDART_INF_F;
        #pragma unroll
        for (int j = 0; j < 8; j++) {
            #pragma unroll
            for (int i = 0; i < 4; i++) s[j][i] *= scale;
            rmax0 = fmaxf(rmax0, fmaxf(s[j][0], s[j][1]));
            rmax1 = fmaxf(rmax1, fmaxf(s[j][2], s[j][3]));
        }
        rmax0 = fmaxf(rmax0, __shfl_xor_sync(0xffffffffu, rmax0, 1));
        rmax0 = fmaxf(rmax0, __shfl_xor_sync(0xffffffffu, rmax0, 2));
        rmax1 = fmaxf(rmax1, __shfl_xor_sync(0xffffffffu, rmax1, 1));
        rmax1 = fmaxf(rmax1, __shfl_xor_sync(0xffffffffu, rmax1, 2));

        float mn0 = fmaxf(m0, rmax0), mn1 = fmaxf(m1, rmax1);
        float c0 = __expf(m0 - mn0), c1 = __expf(m1 - mn1);
        m0 = mn0; m1 = mn1;

        float rs0 = 0.f, rs1 = 0.f;
        #pragma unroll
        for (int j = 0; j < 8; j++) {
            s[j][0] = __expf(s[j][0] - mn0); rs0 += s[j][0];
            s[j][1] = __expf(s[j][1] - mn0); rs0 += s[j][1];
            s[j][2] = __expf(s[j][2] - mn1); rs1 += s[j][2];
            s[j][3] = __expf(s[j][3] - mn1); rs1 += s[j][3];
        }
        rs0 += __shfl_xor_sync(0xffffffffu, rs0, 1);
        rs0 += __shfl_xor_sync(0xffffffffu, rs0, 2);
        rs1 += __shfl_xor_sync(0xffffffffu, rs1, 1);
        rs1 += __shfl_xor_sync(0xffffffffu, rs1, 2);
        l0 = l0 * c0 + rs0;
        l1 = l1 * c1 + rs1;

        #pragma unroll
        for (int j = 0; j < 8; j++) {
            o[j][0] *= c0; o[j][1] *= c0;
            o[j][2] *= c1; o[j][3] *= c1;
        }

        // ---- O += P V (3-pass, P packed hi/lo in registers)
        #pragma unroll
        for (int kk = 0; kk < 4; kk++) {
            uint32_t ph[4], pl[4];
            pack_hilo(s[2 * kk][0],     s[2 * kk][1],     ph[0], pl[0]);
            pack_hilo(s[2 * kk][2],     s[2 * kk][3],     ph[1], pl[1]);
            pack_hilo(s[2 * kk + 1][0], s[2 * kk + 1][1], ph[2], pl[2]);
            pack_hilo(s[2 * kk + 1][2], s[2 * kk + 1][3], ph[3], pl[3]);
            #pragma unroll
            for (int np = 0; np < 4; np++) {
                uint32_t vh4[4], vl4[4];
                ldsm_x4_t(vh4, st + 2 * A_KV + v_off + kk * 16 * ROWA + np * 32);
                ldsm_x4_t(vl4, st + 3 * A_KV + v_off + kk * 16 * ROWA + np * 32);
                mma_bf16(o[np * 2 + 0], ph, vh4[0], vh4[1]);
                mma_bf16(o[np * 2 + 1], ph, vh4[2], vh4[3]);
                mma_bf16(o[np * 2 + 0], ph, vl4[0], vl4[1]);
                mma_bf16(o[np * 2 + 1], ph, vl4[2], vl4[3]);
                mma_bf16(o[np * 2 + 0], pl, vh4[0], vh4[1]);
                mma_bf16(o[np * 2 + 1], pl, vh4[2], vh4[3]);
            }
        }

        __syncthreads();
        if (it + 2 < 16) {
            uint32_t dstg = sKV + (it & 1) * A_STG;
            #pragma unroll
            for (int mat = 0; mat < 4; mat++) {
                #pragma unroll
                for (int cc = 0; cc < 2; cc++) {
                    int ch = lc + cc * 4;
                    CP_ASYNC16(dstg + mat * A_KV + lr * ROWA + ch * 16,
                               kv_src[mat] + (size_t)((it + 2) * 64 + lr) * DD + ch * 8);
                }
            }
            CP_COMMIT();
        }
    }

    // ---- epilogue: normalize + store to AO [b][s][h*64+d] fp32
    float inv0 = 1.f / l0, inv1 = 1.f / l1;
    int r0 = q0 + wid * 16 + (lane >> 2);
    float* row0 = AO + (size_t)(b * SS + r0) * EE + h * DD;
    float* row1 = row0 + (size_t)8 * EE;
    int c0l = (lane & 3) * 2;
    #pragma unroll
    for (int j = 0; j < 8; j++) {
        float2 w0 = {o[j][0] * inv0, o[j][1] * inv0};
        float2 w1 = {o[j][2] * inv1, o[j][3] * inv1};
        *(float2*)&row0[j * 8 + c0l] = w0;
        *(float2*)&row1[j * 8 + c0l] = w1;
    }
}

// ---------------------------------------------------------------------------
// Launch
// ---------------------------------------------------------------------------
extern "C" void kernel_launch(void* const* d_in, const int* in_sizes, int n_in,
                              void* d_out, int out_size)
{
    const float* X   = (const float*)d_in[0];
    const float* rot = (const float*)d_in[1];
    const float* W[4]  = {(const float*)d_in[2], (const float*)d_in[4],
                          (const float*)d_in[6], (const float*)d_in[8]};
    const float* Bv[4] = {(const float*)d_in[3], (const float*)d_in[5],
                          (const float*)d_in[7], (const float*)d_in[9]};
    float* out = (float*)d_out;

    float *Qp, *Kp, *Vp, *AOp;
    __nv_bfloat16 *Xhi, *Xlo, *AOhi, *AOlo, *Whi, *Wlo;
    __nv_bfloat16 *aQh, *aQl, *aKh, *aKl, *aVh, *aVl;
    cudaGetSymbolAddress((void**)&Qp,   g_Q);
    cudaGetSymbolAddress((void**)&Kp,   g_K);
    cudaGetSymbolAddress((void**)&Vp,   g_V);
    cudaGetSymbolAddress((void**)&AOp,  g_AO);
    cudaGetSymbolAddress((void**)&Xhi,  g_Xhi);
    cudaGetSymbolAddress((void**)&Xlo,  g_Xlo);
    cudaGetSymbolAddress((void**)&AOhi, g_AOhi);
    cudaGetSymbolAddress((void**)&AOlo, g_AOlo);
    cudaGetSymbolAddress((void**)&Whi,  g_Whi);
    cudaGetSymbolAddress((void**)&Wlo,  g_Wlo);
    cudaGetSymbolAddress((void**)&aQh,  g_aQh);
    cudaGetSymbolAddress((void**)&aQl,  g_aQl);
    cudaGetSymbolAddress((void**)&aKh,  g_aKh);
    cudaGetSymbolAddress((void**)&aKl,  g_aKl);
    cudaGetSymbolAddress((void**)&aVh,  g_aVh);
    cudaGetSymbolAddress((void**)&aVl,  g_aVl);

    cudaFuncSetAttribute(gemm_hmma_kernel,
                         cudaFuncAttributeMaxDynamicSharedMemorySize, GEMM_SMEM);
    cudaFuncSetAttribute(attn_hmma_kernel,
                         cudaFuncAttributeMaxDynamicSharedMemorySize, ATTN_SMEM);

    for (int i = 0; i < 4; i++)
        transpose_split_kernel<<<dim3(32, 32), dim3(32, 32)>>>(
            W[i], Whi + (size_t)i * EE * EE, Wlo + (size_t)i * EE * EE);

    split_convert_kernel<<<(MM * EE / 4 + 255) / 256, 256>>>(X, Xhi, Xlo, MM * EE / 4);

    dim3 gemm_grid(EE / 128, MM / 128);
    gemm_hmma_kernel<<<gemm_grid, 256, GEMM_SMEM>>>(
        Xhi, Xlo, Whi + 0 * (size_t)EE * EE, Wlo + 0 * (size_t)EE * EE, Bv[0], Qp);
    gemm_hmma_kernel<<<gemm_grid, 256, GEMM_SMEM>>>(
        Xhi, Xlo, Whi + 1 * (size_t)EE * EE, Wlo + 1 * (size_t)EE * EE, Bv[1], Kp);
    gemm_hmma_kernel<<<gemm_grid, 256, GEMM_SMEM>>>(
        Xhi, Xlo, Whi + 2 * (size_t)EE * EE, Wlo + 2 * (size_t)EE * EE, Bv[2], Vp);

    int rope_total = BB * SS * HH * 32;
    rope_split_kernel<<<(rope_total + 255) / 256, 256>>>(
        Qp, Kp, rot, aQh, aQl, aKh, aKl);
    v_split_kernel<<<(MM * EE / 4 + 255) / 256, 256>>>(Vp, aVh, aVl);

    attn_hmma_kernel<<<dim3(SS / 128, BB * HH), 256, ATTN_SMEM>>>(
        aQh, aQl, aKh, aKl, aVh, aVl, AOp);

    split_convert_kernel<<<(MM * EE / 4 + 255) / 256, 256>>>(AOp, AOhi, AOlo, MM * EE / 4);

    gemm_hmma_kernel<<<gemm_grid, 256, GEMM_SMEM>>>(
        AOhi, AOlo, Whi + 3 * (size_t)EE * EE, Wlo + 3 * (size_t)EE * EE, Bv[3], out);
}

// round 7
// speedup vs baseline: 2.2703x; 1.0767x over previous
#include <cuda_runtime.h>
#include <cuda_bf16.h>
#include <math_constants.h>
#include <cstdint>

// Problem constants
#define BB 8
#define SS 1024
#define EE 1024
#define HH 16
#define DD 64
#define MM (BB * SS)   // 8192

// ---------------------------------------------------------------------------
// Scratch (device globals — no allocation allowed)
// ---------------------------------------------------------------------------
__device__ __nv_bfloat16 g_Xhi[MM * EE];
__device__ __nv_bfloat16 g_Xlo[MM * EE];
__device__ __nv_bfloat16 g_AOhi[MM * EE];
__device__ __nv_bfloat16 g_AOlo[MM * EE];
// Attention operands, head-major [b][h][s][d], bf16 hi/lo
__device__ __nv_bfloat16 g_aQh[MM * EE];
__device__ __nv_bfloat16 g_aQl[MM * EE];
__device__ __nv_bfloat16 g_aKh[MM * EE];
__device__ __nv_bfloat16 g_aKl[MM * EE];
__device__ __nv_bfloat16 g_aVh[MM * EE];
__device__ __nv_bfloat16 g_aVl[MM * EE];
// Transposed weights: [N][K] bf16, hi/lo split. Index: 0=q,1=k,2=v,3=o
__device__ __nv_bfloat16 g_Whi[4][EE * EE];
__device__ __nv_bfloat16 g_Wlo[4][EE * EE];
// RoPE tables
__device__ float g_cos[SS * 32];
__device__ float g_sin[SS * 32];

// ---------------------------------------------------------------------------
// Helpers
// ---------------------------------------------------------------------------
__device__ __forceinline__ uint32_t smem_u32(const void* p) {
    uint32_t a;
    asm("{ .reg .u64 t; cvta.to.shared.u64 t, %1; cvt.u32.u64 %0, t; }"
        : "=r"(a) : "l"(p));
    return a;
}

__device__ __forceinline__ void ldsm_x4(uint32_t* r, uint32_t addr) {
    asm volatile("ldmatrix.sync.aligned.m8n8.x4.shared.b16 {%0,%1,%2,%3}, [%4];"
                 : "=r"(r[0]), "=r"(r[1]), "=r"(r[2]), "=r"(r[3]) : "r"(addr));
}

__device__ __forceinline__ void ldsm_x4_t(uint32_t* r, uint32_t addr) {
    asm volatile("ldmatrix.sync.aligned.m8n8.x4.trans.shared.b16 {%0,%1,%2,%3}, [%4];"
                 : "=r"(r[0]), "=r"(r[1]), "=r"(r[2]), "=r"(r[3]) : "r"(addr));
}

__device__ __forceinline__ void mma_bf16(float* d, const uint32_t* a,
                                         uint32_t b0, uint32_t b1) {
    asm volatile(
        "mma.sync.aligned.m16n8k16.row.col.f32.bf16.bf16.f32 "
        "{%0,%1,%2,%3}, {%4,%5,%6,%7}, {%8,%9}, {%0,%1,%2,%3};"
        : "+f"(d[0]), "+f"(d[1]), "+f"(d[2]), "+f"(d[3])
        : "r"(a[0]), "r"(a[1]), "r"(a[2]), "r"(a[3]), "r"(b0), "r"(b1));
}

// Split two floats into packed bf16 hi pair + lo pair
__device__ __forceinline__ void pack_hilo(float x, float y,
                                          uint32_t& h, uint32_t& l) {
    __nv_bfloat162 hv = __floats2bfloat162_rn(x, y);
    float hx = __bfloat162float(hv.x), hy = __bfloat162float(hv.y);
    __nv_bfloat162 lv = __floats2bfloat162_rn(x - hx, y - hy);
    h = reinterpret_cast<uint32_t&>(hv);
    l = reinterpret_cast<uint32_t&>(lv);
}

#define CP_ASYNC16(dst, src) \
    asm volatile("cp.async.cg.shared.global [%0], [%1], 16;\n" \
                 :: "r"(dst), "l"(src) : "memory")
#define CP_COMMIT() asm volatile("cp.async.commit_group;\n" ::: "memory")

// ---------------------------------------------------------------------------
// RoPE cos/sin tables
// ---------------------------------------------------------------------------
__global__ void rope_tab_kernel(const float* __restrict__ freqs,
                                float* __restrict__ ct, float* __restrict__ st)
{
    int i = blockIdx.x * blockDim.x + threadIdx.x;
    if (i >= SS * 32) return;
    float s, c;
    sincosf(freqs[i], &s, &c);
    ct[i] = c;
    st[i] = s;
}

// ---------------------------------------------------------------------------
// fp32 -> bf16 hi/lo split (X only)
// ---------------------------------------------------------------------------
__global__ void split_convert_kernel(const float* __restrict__ X,
                                     __nv_bfloat16* __restrict__ hi,
                                     __nv_bfloat16* __restrict__ lo, int n4)
{
    int i = blockIdx.x * blockDim.x + threadIdx.x;
    if (i >= n4) return;
    float4 v = *(const float4*)&X[i * 4];
    float vv[4] = {v.x, v.y, v.z, v.w};
    #pragma unroll
    for (int j = 0; j < 4; j++) {
        __nv_bfloat16 h = __float2bfloat16(vv[j]);
        float r = vv[j] - __bfloat162float(h);
        hi[i * 4 + j] = h;
        lo[i * 4 + j] = __float2bfloat16(r);
    }
}

// ---------------------------------------------------------------------------
// Weight transpose + split, all 4 weights in one launch (z selects)
// ---------------------------------------------------------------------------
__global__ __launch_bounds__(1024) void transpose_split_kernel(
    const float* __restrict__ w0, const float* __restrict__ w1,
    const float* __restrict__ w2, const float* __restrict__ w3,
    __nv_bfloat16* __restrict__ WhiA, __nv_bfloat16* __restrict__ WloA)
{
    __shared__ float t[32][33];
    int z = blockIdx.z;
    const float* W = (z == 0) ? w0 : (z == 1) ? w1 : (z == 2) ? w2 : w3;
    __nv_bfloat16* Whi = WhiA + (size_t)z * EE * EE;
    __nv_bfloat16* Wlo = WloA + (size_t)z * EE * EE;

    int k = blockIdx.y * 32 + threadIdx.y;
    int n = blockIdx.x * 32 + threadIdx.x;
    t[threadIdx.y][threadIdx.x] = W[(size_t)k * EE + n];
    __syncthreads();
    int nn = blockIdx.x * 32 + threadIdx.y;
    int kk = blockIdx.y * 32 + threadIdx.x;
    float v = t[threadIdx.x][threadIdx.y];
    __nv_bfloat16 h = __float2bfloat16(v);
    float r = v - __bfloat162float(h);
    Whi[(size_t)nn * EE + kk] = h;
    Wlo[(size_t)nn * EE + kk] = __float2bfloat16(r);
}

// ---------------------------------------------------------------------------
// HMMA bf16 3-pass split GEMM, warp tile 32x64 (warp owns a full head).
// EPI 0: fp32 + bias -> Cf (O projection)
// EPI 1: merged QKV; z=0/1 -> bias + RoPE + split, head-major; z=2 -> V split
// ---------------------------------------------------------------------------
#define BKG 32
#define NIT (EE / BKG)          // 32
#define ROWB 80
#define MATB (128 * ROWB)
#define OAH 0
#define OAL (1 * MATB)
#define OBH (2 * MATB)
#define OBL (3 * MATB)
#define STGB (4 * MATB)
#define GSTAGES 3
#define GEMM_SMEM (GSTAGES * STGB)  // 122880 B

template<int EPI>
__global__ __launch_bounds__(256) void gemm_hmma_t(
    const __nv_bfloat16* __restrict__ Ahi, const __nv_bfloat16* __restrict__ Alo,
    const __nv_bfloat16* __restrict__ WhiA, const __nv_bfloat16* __restrict__ WloA,
    const float* __restrict__ b0, const float* __restrict__ b1,
    const float* __restrict__ b2,
    float* __restrict__ Cf,
    __nv_bfloat16* __restrict__ O0h, __nv_bfloat16* __restrict__ O0l,
    __nv_bfloat16* __restrict__ O1h, __nv_bfloat16* __restrict__ O1l,
    __nv_bfloat16* __restrict__ O2h, __nv_bfloat16* __restrict__ O2l,
    const float* __restrict__ costab, const float* __restrict__ sintab)
{
    extern __shared__ char smraw[];
    const uint32_t sb = smem_u32(smraw);
    const int tid  = threadIdx.x;
    const int wid  = tid >> 5;
    const int lane = tid & 31;
    const int m0 = blockIdx.y * 128;
    const int n0 = blockIdx.x * 128;
    const int wm = (wid & 3) * 32;        // warp row offset
    const int wn = (wid >> 2) * 64;       // warp col offset (full head)
    const int z  = (EPI == 1) ? blockIdx.z : 0;

    const __nv_bfloat16* Bhi = WhiA + (size_t)z * EE * EE;
    const __nv_bfloat16* Blo = WloA + (size_t)z * EE * EE;

    const int lr = tid >> 2;
    const int lc = tid & 3;
    const __nv_bfloat16* gsrc[4] = {
        Ahi + (size_t)(m0 + lr) * EE + lc * 8,
        Alo + (size_t)(m0 + lr) * EE + lc * 8,
        Bhi + (size_t)(n0 + lr) * EE + lc * 8,
        Blo + (size_t)(n0 + lr) * EE + lc * 8
    };
    const uint32_t dst0 = sb + lr * ROWB + lc * 16;

    const uint32_t a_off = (wm + (lane & 15)) * ROWB + (lane >> 4) * 16;
    const uint32_t b_off = (wn + ((lane >> 4) << 3) + (lane & 7)) * ROWB
                         + ((lane >> 3) & 1) * 16;

    float d[2][8][4];
    #pragma unroll
    for (int mt = 0; mt < 2; mt++)
        #pragma unroll
        for (int nt = 0; nt < 8; nt++)
            #pragma unroll
            for (int i = 0; i < 4; i++) d[mt][nt][i] = 0.f;

    #pragma unroll
    for (int s = 0; s < 2; s++) {
        #pragma unroll
        for (int mat = 0; mat < 4; mat++) {
            #pragma unroll
            for (int p = 0; p < 2; p++) {
                uint32_t dst = dst0 + s * STGB + mat * MATB + p * 64 * ROWB;
                const void* g = gsrc[mat] + (size_t)p * 64 * EE + s * BKG;
                CP_ASYNC16(dst, g);
            }
        }
        CP_COMMIT();
    }

    for (int it = 0; it < NIT; it++) {
        if (it < NIT - 2)
            asm volatile("cp.async.wait_group 1;\n" ::: "memory");
        else
            asm volatile("cp.async.wait_group 0;\n" ::: "memory");
        __syncthreads();

        if (it + 2 < NIT) {
            int s = (it + 2) % GSTAGES;
            int k0 = (it + 2) * BKG;
            #pragma unroll
            for (int mat = 0; mat < 4; mat++) {
                #pragma unroll
                for (int p = 0; p < 2; p++) {
                    uint32_t dst = dst0 + s * STGB + mat * MATB + p * 64 * ROWB;
                    const void* g = gsrc[mat] + (size_t)p * 64 * EE + k0;
                    CP_ASYNC16(dst, g);
                }
            }
            CP_COMMIT();
        }

        const uint32_t st = sb + (it % GSTAGES) * STGB;
        #pragma unroll
        for (int kc = 0; kc < 2; kc++) {
            uint32_t ah[2][4], al[2][4], bh[4][4], bl[4][4];
            #pragma unroll
            for (int mt = 0; mt < 2; mt++) {
                ldsm_x4(ah[mt], st + OAH + a_off + mt * 16 * ROWB + kc * 32);
                ldsm_x4(al[mt], st + OAL + a_off + mt * 16 * ROWB + kc * 32);
            }
            #pragma unroll
            for (int nb = 0; nb < 4; nb++) {
                ldsm_x4(bh[nb], st + OBH + b_off + nb * 16 * ROWB + kc * 32);
                ldsm_x4(bl[nb], st + OBL + b_off + nb * 16 * ROWB + kc * 32);
            }
            #pragma unroll
            for (int mt = 0; mt < 2; mt++) {
                #pragma unroll
                for (int nt = 0; nt < 8; nt++) {
                    int nb = nt >> 1, sc = (nt & 1) * 2;
                    mma_bf16(d[mt][nt], ah[mt], bh[nb][sc], bh[nb][sc + 1]);
                    mma_bf16(d[mt][nt], ah[mt], bl[nb][sc], bl[nb][sc + 1]);
                    mma_bf16(d[mt][nt], al[mt], bh[nb][sc], bh[nb][sc + 1]);
                }
            }
        }
        __syncthreads();
    }

    if (EPI == 0) {
        // fp32 + bias epilogue (O projection)
        #pragma unroll
        for (int mt = 0; mt < 2; mt++) {
            int r = m0 + wm + mt * 16 + (lane >> 2);
            #pragma unroll
            for (int nt = 0; nt < 8; nt++) {
                int c = n0 + wn + nt * 8 + (lane & 3) * 2;
                float2 bb = *(const float2*)&b0[c];
                float2 o0 = {d[mt][nt][0] + bb.x, d[mt][nt][1] + bb.y};
                float2 o1 = {d[mt][nt][2] + bb.x, d[mt][nt][3] + bb.y};
                *(float2*)&Cf[(size_t)r * EE + c] = o0;
                *(float2*)&Cf[(size_t)(r + 8) * EE + c] = o1;
            }
        }
    } else {
        const float* bias = (z == 0) ? b0 : (z == 1) ? b1 : b2;
        // bias add into accumulators
        #pragma unroll
        for (int mt = 0; mt < 2; mt++)
            #pragma unroll
            for (int nt = 0; nt < 8; nt++) {
                float2 bb = *(const float2*)&bias[n0 + wn + nt * 8 + (lane & 3) * 2];
                d[mt][nt][0] += bb.x; d[mt][nt][1] += bb.y;
                d[mt][nt][2] += bb.x; d[mt][nt][3] += bb.y;
            }

        const int head = (n0 + wn) >> 6;
        __nv_bfloat16* Oh = (z == 0) ? O0h : (z == 1) ? O1h : O2h;
        __nv_bfloat16* Ol = (z == 0) ? O0l : (z == 1) ? O1l : O2l;

        if (z < 2) {
            // RoPE + hi/lo split, head-major store
            #pragma unroll
            for (int mt = 0; mt < 2; mt++) {
                #pragma unroll
                for (int rr = 0; rr < 2; rr++) {
                    int r = m0 + wm + mt * 16 + (lane >> 2) + rr * 8;
                    int b = r >> 10, s = r & (SS - 1);
                    size_t ob = ((size_t)(b * HH + head) * SS + s) * DD;
                    const float* cs = costab + s * 32;
                    const float* sn = sintab + s * 32;
                    #pragma unroll
                    for (int nt = 0; nt < 4; nt++) {
                        int dh = nt * 8 + (lane & 3) * 2;
                        float2 c2 = *(const float2*)&cs[dh];
                        float2 s2 = *(const float2*)&sn[dh];
                        float x1a = d[mt][nt][rr * 2 + 0];
                        float x1b = d[mt][nt][rr * 2 + 1];
                        float x2a = d[mt][nt + 4][rr * 2 + 0];
                        float x2b = d[mt][nt + 4][rr * 2 + 1];
                        float o1a = x1a * c2.x - x2a * s2.x;
                        float o1b = x1b * c2.y - x2b * s2.y;
                        float o2a = x2a * c2.x + x1a * s2.x;
                        float o2b = x2b * c2.y + x1b * s2.y;
                        uint32_t h1, l1, h2, l2;
                        pack_hilo(o1a, o1b, h1, l1);
                        pack_hilo(o2a, o2b, h2, l2);
                        *(uint32_t*)&Oh[ob + dh]      = h1;
                        *(uint32_t*)&Ol[ob + dh]      = l1;
                        *(uint32_t*)&Oh[ob + dh + 32] = h2;
                        *(uint32_t*)&Ol[ob + dh + 32] = l2;
                    }
                }
            }
        } else {
            // V: hi/lo split, head-major store
            #pragma unroll
            for (int mt = 0; mt < 2; mt++) {
                #pragma unroll
                for (int rr = 0; rr < 2; rr++) {
                    int r = m0 + wm + mt * 16 + (lane >> 2) + rr * 8;
                    int b = r >> 10, s = r & (SS - 1);
                    size_t ob = ((size_t)(b * HH + head) * SS + s) * DD;
                    #pragma unroll
                    for (int nt = 0; nt < 8; nt++) {
                        int dh = nt * 8 + (lane & 3) * 2;
                        uint32_t h, l;
                        pack_hilo(d[mt][nt][rr * 2 + 0],
                                  d[mt][nt][rr * 2 + 1], h, l);
                        *(uint32_t*)&Oh[ob + dh] = h;
                        *(uint32_t*)&Ol[ob + dh] = l;
                    }
                }
            }
        }
    }
}

// ---------------------------------------------------------------------------
// HMMA FlashAttention-2, bf16 hi/lo 3-pass; epilogue writes bf16 hi/lo AO.
// ---------------------------------------------------------------------------
#define ROWA 144
#define A_QTILE (128 * ROWA)
#define A_KV (64 * ROWA)
#define A_STG (4 * A_KV)
#define ATTN_SMEM (2 * A_QTILE + 2 * A_STG)   // 110592

__global__ __launch_bounds__(256) void attn_hmma_kernel(
    const __nv_bfloat16* __restrict__ Qh, const __nv_bfloat16* __restrict__ Ql,
    const __nv_bfloat16* __restrict__ Kh, const __nv_bfloat16* __restrict__ Kl,
    const __nv_bfloat16* __restrict__ Vh, const __nv_bfloat16* __restrict__ Vl,
    __nv_bfloat16* __restrict__ AOh, __nv_bfloat16* __restrict__ AOl)
{
    extern __shared__ char smraw[];
    const uint32_t sb = smem_u32(smraw);
    const int tid = threadIdx.x;
    const int wid = tid >> 5;
    const int lane = tid & 31;
    const int bh = blockIdx.y;
    const int b = bh >> 4, h = bh & (HH - 1);
    const int q0 = blockIdx.x * 128;

    const size_t hbase = (size_t)bh * SS * DD;
    const __nv_bfloat16* Qhp = Qh + hbase + (size_t)q0 * DD;
    const __nv_bfloat16* Qlp = Ql + hbase + (size_t)q0 * DD;
    const __nv_bfloat16* kv_src[4] = {Kh + hbase, Kl + hbase,
                                      Vh + hbase, Vl + hbase};

    const uint32_t sQh = sb, sQl = sb + A_QTILE;
    const uint32_t sKV = sb + 2 * A_QTILE;

    const int lr = tid >> 2;
    const int lc = tid & 3;

    #pragma unroll
    for (int p = 0; p < 2; p++) {
        int r = lr + p * 64;
        #pragma unroll
        for (int cc = 0; cc < 2; cc++) {
            int ch = lc + cc * 4;
            CP_ASYNC16(sQh + r * ROWA + ch * 16, Qhp + (size_t)r * DD + ch * 8);
            CP_ASYNC16(sQl + r * ROWA + ch * 16, Qlp + (size_t)r * DD + ch * 8);
        }
    }
    #pragma unroll
    for (int mat = 0; mat < 4; mat++) {
        #pragma unroll
        for (int cc = 0; cc < 2; cc++) {
            int ch = lc + cc * 4;
            CP_ASYNC16(sKV + mat * A_KV + lr * ROWA + ch * 16,
                       kv_src[mat] + (size_t)lr * DD + ch * 8);
        }
    }
    CP_COMMIT();
    #pragma unroll
    for (int mat = 0; mat < 4; mat++) {
        #pragma unroll
        for (int cc = 0; cc < 2; cc++) {
            int ch = lc + cc * 4;
            CP_ASYNC16(sKV + A_STG + mat * A_KV + lr * ROWA + ch * 16,
                       kv_src[mat] + (size_t)(64 + lr) * DD + ch * 8);
        }
    }
    CP_COMMIT();

    asm volatile("cp.async.wait_group 1;\n" ::: "memory");
    __syncthreads();

    const uint32_t a_off = (wid * 16 + (lane & 15)) * ROWA + (lane >> 4) * 16;
    uint32_t qh[4][4], ql[4][4];
    #pragma unroll
    for (int kk = 0; kk < 4; kk++) {
        ldsm_x4(qh[kk], sQh + a_off + kk * 32);
        ldsm_x4(ql[kk], sQl + a_off + kk * 32);
    }

    const uint32_t b_off = (((lane >> 4) << 3) + (lane & 7)) * ROWA
                         + ((lane >> 3) & 1) * 16;
    const uint32_t v_off = (lane & 15) * ROWA + (lane >> 4) * 16;

    float m0 = -CUDART_INF_F, m1 = -CUDART_INF_F, l0 = 0.f, l1 = 0.f;
    float o[8][4];
    #pragma unroll
    for (int j = 0; j < 8; j++)
        #pragma unroll
        for (int i = 0; i < 4; i++) o[j][i] = 0.f;

    const float scale = 0.125f;

    for (int it = 0; it < 16; it++) {
        if (it > 0) {
            if (it < 14)
                asm volatile("cp.async.wait_group 1;\n" ::: "memory");
            else
                asm volatile("cp.async.wait_group 0;\n" ::: "memory");
            __syncthreads();
        }
        const uint32_t st = sKV + (it & 1) * A_STG;

        float s[8][4];
        #pragma unroll
        for (int j = 0; j < 8; j++)
            #pragma unroll
            for (int i = 0; i < 4; i++) s[j][i] = 0.f;

        #pragma unroll
        for (int np = 0; np < 4; np++) {
            #pragma unroll
            for (int kk = 0; kk < 4; kk++) {
                uint32_t kh4[4], kl4[4];
                ldsm_x4(kh4, st + 0 * A_KV + b_off + np * 16 * ROWA + kk * 32);
                ldsm_x4(kl4, st + 1 * A_KV + b_off + np * 16 * ROWA + kk * 32);
                mma_bf16(s[np * 2 + 0], qh[kk], kh4[0], kh4[1]);
                mma_bf16(s[np * 2 + 1], qh[kk], kh4[2], kh4[3]);
                mma_bf16(s[np * 2 + 0], qh[kk], kl4[0], kl4[1]);
                mma_bf16(s[np * 2 + 1], qh[kk], kl4[2], kl4[3]);
                mma_bf16(s[np * 2 + 0], ql[kk], kh4[0], kh4[1]);
                mma_bf16(s[np * 2 + 1], ql[kk], kh4[2], kh4[3]);
            }
        }

        float rmax0 = -CUDART_INF_F, rmax1 = -CUDART_INF_F;
        #pragma unroll
        for (int j = 0; j < 8; j++) {
            #pragma unroll
            for (int i = 0; i < 4; i++) s[j][i] *= scale;
            rmax0 = fmaxf(rmax0, fmaxf(s[j][0], s[j][1]));
            rmax1 = fmaxf(rmax1, fmaxf(s[j][2], s[j][3]));
        }
        rmax0 = fmaxf(rmax0, __shfl_xor_sync(0xffffffffu, rmax0, 1));
        rmax0 = fmaxf(rmax0, __shfl_xor_sync(0xffffffffu, rmax0, 2));
        rmax1 = fmaxf(rmax1, __shfl_xor_sync(0xffffffffu, rmax1, 1));
        rmax1 = fmaxf(rmax1, __shfl_xor_sync(0xffffffffu, rmax1, 2));

        float mn0 = fmaxf(m0, rmax0), mn1 = fmaxf(m1, rmax1);
        float c0 = __expf(m0 - mn0), c1 = __expf(m1 - mn1);
        m0 = mn0; m1 = mn1;

        float rs0 = 0.f, rs1 = 0.f;
        #pragma unroll
        for (int j = 0; j < 8; j++) {
            s[j][0] = __expf(s[j][0] - mn0); rs0 += s[j][0];
            s[j][1] = __expf(s[j][1] - mn0); rs0 += s[j][1];
            s[j][2] = __expf(s[j][2] - mn1); rs1 += s[j][2];
            s[j][3] = __expf(s[j][3] - mn1); rs1 += s[j][3];
        }
        rs0 += __shfl_xor_sync(0xffffffffu, rs0, 1);
        rs0 += __shfl_xor_sync(0xffffffffu, rs0, 2);
        rs1 += __shfl_xor_sync(0xffffffffu, rs1, 1);
        rs1 += __shfl_xor_sync(0xffffffffu, rs1, 2);
        l0 = l0 * c0 + rs0;
        l1 = l1 * c1 + rs1;

        #pragma unroll
        for (int j = 0; j < 8; j++) {
            o[j][0] *= c0; o[j][1] *= c0;
            o[j][2] *= c1; o[j][3] *= c1;
        }

        #pragma unroll
        for (int kk = 0; kk < 4; kk++) {
            uint32_t ph[4], pl[4];
            pack_hilo(s[2 * kk][0],     s[2 * kk][1],     ph[0], pl[0]);
            pack_hilo(s[2 * kk][2],     s[2 * kk][3],     ph[1], pl[1]);
            pack_hilo(s[2 * kk + 1][0], s[2 * kk + 1][1], ph[2], pl[2]);
            pack_hilo(s[2 * kk + 1][2], s[2 * kk + 1][3], ph[3], pl[3]);
            #pragma unroll
            for (int np = 0; np < 4; np++) {
                uint32_t vh4[4], vl4[4];
                ldsm_x4_t(vh4, st + 2 * A_KV + v_off + kk * 16 * ROWA + np * 32);
                ldsm_x4_t(vl4, st + 3 * A_KV + v_off + kk * 16 * ROWA + np * 32);
                mma_bf16(o[np * 2 + 0], ph, vh4[0], vh4[1]);
                mma_bf16(o[np * 2 + 1], ph, vh4[2], vh4[3]);
                mma_bf16(o[np * 2 + 0], ph, vl4[0], vl4[1]);
                mma_bf16(o[np * 2 + 1], ph, vl4[2], vl4[3]);
                mma_bf16(o[np * 2 + 0], pl, vh4[0], vh4[1]);
                mma_bf16(o[np * 2 + 1], pl, vh4[2], vh4[3]);
            }
        }

        __syncthreads();
        if (it + 2 < 16) {
            uint32_t dstg = sKV + (it & 1) * A_STG;
            #pragma unroll
            for (int mat = 0; mat < 4; mat++) {
                #pragma unroll
                for (int cc = 0; cc < 2; cc++) {
                    int ch = lc + cc * 4;
                    CP_ASYNC16(dstg + mat * A_KV + lr * ROWA + ch * 16,
                               kv_src[mat] + (size_t)((it + 2) * 64 + lr) * DD + ch * 8);
                }
            }
            CP_COMMIT();
        }
    }

    // epilogue: normalize + hi/lo split -> AOh/AOl [b][s][h*64+d]
    float inv0 = 1.f / l0, inv1 = 1.f / l1;
    int r0 = q0 + wid * 16 + (lane >> 2);
    size_t base0 = (size_t)(b * SS + r0) * EE + h * DD;
    size_t base1 = base0 + (size_t)8 * EE;
    int c0l = (lane & 3) * 2;
    #pragma unroll
    for (int j = 0; j < 8; j++) {
        uint32_t h0, l0b, h1, l1b;
        pack_hilo(o[j][0] * inv0, o[j][1] * inv0, h0, l0b);
        pack_hilo(o[j][2] * inv1, o[j][3] * inv1, h1, l1b);
        *(uint32_t*)&AOh[base0 + j * 8 + c0l] = h0;
        *(uint32_t*)&AOl[base0 + j * 8 + c0l] = l0b;
        *(uint32_t*)&AOh[base1 + j * 8 + c0l] = h1;
        *(uint32_t*)&AOl[base1 + j * 8 + c0l] = l1b;
    }
}

// ---------------------------------------------------------------------------
// Launch
// ---------------------------------------------------------------------------
extern "C" void kernel_launch(void* const* d_in, const int* in_sizes, int n_in,
                              void* d_out, int out_size)
{
    const float* X   = (const float*)d_in[0];
    const float* rot = (const float*)d_in[1];
    const float* W[4]  = {(const float*)d_in[2], (const float*)d_in[4],
                          (const float*)d_in[6], (const float*)d_in[8]};
    const float* Bv[4] = {(const float*)d_in[3], (const float*)d_in[5],
                          (const float*)d_in[7], (const float*)d_in[9]};
    float* out = (float*)d_out;

    __nv_bfloat16 *Xhi, *Xlo, *AOhi, *AOlo, *Whi, *Wlo;
    __nv_bfloat16 *aQh, *aQl, *aKh, *aKl, *aVh, *aVl;
    float *ctab, *stab;
    cudaGetSymbolAddress((void**)&Xhi,  g_Xhi);
    cudaGetSymbolAddress((void**)&Xlo,  g_Xlo);
    cudaGetSymbolAddress((void**)&AOhi, g_AOhi);
    cudaGetSymbolAddress((void**)&AOlo, g_AOlo);
    cudaGetSymbolAddress((void**)&Whi,  g_Whi);
    cudaGetSymbolAddress((void**)&Wlo,  g_Wlo);
    cudaGetSymbolAddress((void**)&aQh,  g_aQh);
    cudaGetSymbolAddress((void**)&aQl,  g_aQl);
    cudaGetSymbolAddress((void**)&aKh,  g_aKh);
    cudaGetSymbolAddress((void**)&aKl,  g_aKl);
    cudaGetSymbolAddress((void**)&aVh,  g_aVh);
    cudaGetSymbolAddress((void**)&aVl,  g_aVl);
    cudaGetSymbolAddress((void**)&ctab, g_cos);
    cudaGetSymbolAddress((void**)&stab, g_sin);

    cudaFuncSetAttribute(gemm_hmma_t<0>,
                         cudaFuncAttributeMaxDynamicSharedMemorySize, GEMM_SMEM);
    cudaFuncSetAttribute(gemm_hmma_t<1>,
                         cudaFuncAttributeMaxDynamicSharedMemorySize, GEMM_SMEM);
    cudaFuncSetAttribute(attn_hmma_kernel,
                         cudaFuncAttributeMaxDynamicSharedMemorySize, ATTN_SMEM);

    rope_tab_kernel<<<(SS * 32 + 255) / 256, 256>>>(rot, ctab, stab);
    transpose_split_kernel<<<dim3(32, 32, 4), dim3(32, 32)>>>(
        W[0], W[1], W[2], W[3], Whi, Wlo);
    split_convert_kernel<<<(MM * EE / 4 + 255) / 256, 256>>>(
        X, Xhi, Xlo, MM * EE / 4);

    // Merged QKV projections with fused rope/split epilogues
    gemm_hmma_t<1><<<dim3(8, 64, 3), 256, GEMM_SMEM>>>(
        Xhi, Xlo, Whi, Wlo, Bv[0], Bv[1], Bv[2],
        nullptr, aQh, aQl, aKh, aKl, aVh, aVl, ctab, stab);

    attn_hmma_kernel<<<dim3(SS / 128, BB * HH), 256, ATTN_SMEM>>>(
        aQh, aQl, aKh, aKl, aVh, aVl, AOhi, AOlo);

    // O projection
    gemm_hmma_t<0><<<dim3(8, 64, 1), 256, GEMM_SMEM>>>(
        AOhi, AOlo, Whi + 3 * (size_t)EE * EE, Wlo + 3 * (size_t)EE * EE,
        Bv[3], nullptr, nullptr,
        out, nullptr, nullptr, nullptr, nullptr, nullptr, nullptr, ctab, stab);
}

// round 8
// speedup vs baseline: 2.2706x; 1.0001x over previous
#include <cuda_runtime.h>
#include <cuda_bf16.h>
#include <math_constants.h>
#include <cstdint>

// Problem constants
#define BB 8
#define SS 1024
#define EE 1024
#define HH 16
#define DD 64
#define MM (BB * SS)   // 8192

// ---------------------------------------------------------------------------
// Scratch (device globals — no allocation allowed)
// ---------------------------------------------------------------------------
__device__ __nv_bfloat16 g_Xhi[MM * EE];
__device__ __nv_bfloat16 g_Xlo[MM * EE];
__device__ __nv_bfloat16 g_AOhi[MM * EE];
__device__ __nv_bfloat16 g_AOlo[MM * EE];
// Attention operands, head-major [b][h][s][d], bf16 hi/lo
__device__ __nv_bfloat16 g_aQh[MM * EE];
__device__ __nv_bfloat16 g_aQl[MM * EE];
__device__ __nv_bfloat16 g_aKh[MM * EE];
__device__ __nv_bfloat16 g_aKl[MM * EE];
__device__ __nv_bfloat16 g_aVh[MM * EE];
__device__ __nv_bfloat16 g_aVl[MM * EE];
// Transposed weights: [N][K] bf16, hi/lo split. Index: 0=q,1=k,2=v,3=o
__device__ __nv_bfloat16 g_Whi[4][EE * EE];
__device__ __nv_bfloat16 g_Wlo[4][EE * EE];
// RoPE tables
__device__ float g_cos[SS * 32];
__device__ float g_sin[SS * 32];

// ---------------------------------------------------------------------------
// Helpers
// ---------------------------------------------------------------------------
__device__ __forceinline__ uint32_t smem_u32(const void* p) {
    uint32_t a;
    asm("{ .reg .u64 t; cvta.to.shared.u64 t, %1; cvt.u32.u64 %0, t; }"
        : "=r"(a) : "l"(p));
    return a;
}

__device__ __forceinline__ void ldsm_x4(uint32_t* r, uint32_t addr) {
    asm volatile("ldmatrix.sync.aligned.m8n8.x4.shared.b16 {%0,%1,%2,%3}, [%4];"
                 : "=r"(r[0]), "=r"(r[1]), "=r"(r[2]), "=r"(r[3]) : "r"(addr));
}

__device__ __forceinline__ void ldsm_x4_t(uint32_t* r, uint32_t addr) {
    asm volatile("ldmatrix.sync.aligned.m8n8.x4.trans.shared.b16 {%0,%1,%2,%3}, [%4];"
                 : "=r"(r[0]), "=r"(r[1]), "=r"(r[2]), "=r"(r[3]) : "r"(addr));
}

__device__ __forceinline__ void mma_bf16(float* d, const uint32_t* a,
                                         uint32_t b0, uint32_t b1) {
    asm volatile(
        "mma.sync.aligned.m16n8k16.row.col.f32.bf16.bf16.f32 "
        "{%0,%1,%2,%3}, {%4,%5,%6,%7}, {%8,%9}, {%0,%1,%2,%3};"
        : "+f"(d[0]), "+f"(d[1]), "+f"(d[2]), "+f"(d[3])
        : "r"(a[0]), "r"(a[1]), "r"(a[2]), "r"(a[3]), "r"(b0), "r"(b1));
}

// Split two floats into packed bf16 hi pair + lo pair
__device__ __forceinline__ void pack_hilo(float x, float y,
                                          uint32_t& h, uint32_t& l) {
    __nv_bfloat162 hv = __floats2bfloat162_rn(x, y);
    float hx = __bfloat162float(hv.x), hy = __bfloat162float(hv.y);
    __nv_bfloat162 lv = __floats2bfloat162_rn(x - hx, y - hy);
    h = reinterpret_cast<uint32_t&>(hv);
    l = reinterpret_cast<uint32_t&>(lv);
}

#define CP_ASYNC16(dst, src) \
    asm volatile("cp.async.cg.shared.global [%0], [%1], 16;\n" \
                 :: "r"(dst), "l"(src) : "memory")
#define CP_COMMIT() asm volatile("cp.async.commit_group;\n" ::: "memory")

// ---------------------------------------------------------------------------
// RoPE cos/sin tables
// ---------------------------------------------------------------------------
__global__ void rope_tab_kernel(const float* __restrict__ freqs,
                                float* __restrict__ ct, float* __restrict__ st)
{
    int i = blockIdx.x * blockDim.x + threadIdx.x;
    if (i >= SS * 32) return;
    float s, c;
    sincosf(freqs[i], &s, &c);
    ct[i] = c;
    st[i] = s;
}

// ---------------------------------------------------------------------------
// fp32 -> bf16 hi/lo split (X only)
// ---------------------------------------------------------------------------
__global__ void split_convert_kernel(const float* __restrict__ X,
                                     __nv_bfloat16* __restrict__ hi,
                                     __nv_bfloat16* __restrict__ lo, int n4)
{
    int i = blockIdx.x * blockDim.x + threadIdx.x;
    if (i >= n4) return;
    float4 v = *(const float4*)&X[i * 4];
    float vv[4] = {v.x, v.y, v.z, v.w};
    #pragma unroll
    for (int j = 0; j < 4; j++) {
        __nv_bfloat16 h = __float2bfloat16(vv[j]);
        float r = vv[j] - __bfloat162float(h);
        hi[i * 4 + j] = h;
        lo[i * 4 + j] = __float2bfloat16(r);
    }
}

// ---------------------------------------------------------------------------
// Weight transpose + split, all 4 weights in one launch (z selects)
// ---------------------------------------------------------------------------
__global__ __launch_bounds__(1024) void transpose_split_kernel(
    const float* __restrict__ w0, const float* __restrict__ w1,
    const float* __restrict__ w2, const float* __restrict__ w3,
    __nv_bfloat16* __restrict__ WhiA, __nv_bfloat16* __restrict__ WloA)
{
    __shared__ float t[32][33];
    int z = blockIdx.z;
    const float* W = (z == 0) ? w0 : (z == 1) ? w1 : (z == 2) ? w2 : w3;
    __nv_bfloat16* Whi = WhiA + (size_t)z * EE * EE;
    __nv_bfloat16* Wlo = WloA + (size_t)z * EE * EE;

    int k = blockIdx.y * 32 + threadIdx.y;
    int n = blockIdx.x * 32 + threadIdx.x;
    t[threadIdx.y][threadIdx.x] = W[(size_t)k * EE + n];
    __syncthreads();
    int nn = blockIdx.x * 32 + threadIdx.y;
    int kk = blockIdx.y * 32 + threadIdx.x;
    float v = t[threadIdx.x][threadIdx.y];
    __nv_bfloat16 h = __float2bfloat16(v);
    float r = v - __bfloat162float(h);
    Whi[(size_t)nn * EE + kk] = h;
    Wlo[(size_t)nn * EE + kk] = __float2bfloat16(r);
}

// ---------------------------------------------------------------------------
// HMMA bf16 3-pass split GEMM, warp tile 32x64 (warp owns a full head).
// EPI 0: fp32 + bias -> Cf (O projection)
// EPI 1: merged QKV; z=0/1 -> bias + RoPE + split, head-major; z=2 -> V split
// ---------------------------------------------------------------------------
#define BKG 32
#define NIT (EE / BKG)          // 32
#define ROWB 80
#define MATB (128 * ROWB)
#define OAH 0
#define OAL (1 * MATB)
#define OBH (2 * MATB)
#define OBL (3 * MATB)
#define STGB (4 * MATB)
#define GSTAGES 3
#define GEMM_SMEM (GSTAGES * STGB)  // 122880 B

template<int EPI>
__global__ __launch_bounds__(256) void gemm_hmma_t(
    const __nv_bfloat16* __restrict__ Ahi, const __nv_bfloat16* __restrict__ Alo,
    const __nv_bfloat16* __restrict__ WhiA, const __nv_bfloat16* __restrict__ WloA,
    const float* __restrict__ b0, const float* __restrict__ b1,
    const float* __restrict__ b2,
    float* __restrict__ Cf,
    __nv_bfloat16* __restrict__ O0h, __nv_bfloat16* __restrict__ O0l,
    __nv_bfloat16* __restrict__ O1h, __nv_bfloat16* __restrict__ O1l,
    __nv_bfloat16* __restrict__ O2h, __nv_bfloat16* __restrict__ O2l,
    const float* __restrict__ costab, const float* __restrict__ sintab)
{
    extern __shared__ char smraw[];
    const uint32_t sb = smem_u32(smraw);
    const int tid  = threadIdx.x;
    const int wid  = tid >> 5;
    const int lane = tid & 31;
    const int m0 = blockIdx.y * 128;
    const int n0 = blockIdx.x * 128;
    const int wm = (wid & 3) * 32;        // warp row offset
    const int wn = (wid >> 2) * 64;       // warp col offset (full head)
    const int z  = (EPI == 1) ? blockIdx.z : 0;

    const __nv_bfloat16* Bhi = WhiA + (size_t)z * EE * EE;
    const __nv_bfloat16* Blo = WloA + (size_t)z * EE * EE;

    const int lr = tid >> 2;
    const int lc = tid & 3;
    const __nv_bfloat16* gsrc[4] = {
        Ahi + (size_t)(m0 + lr) * EE + lc * 8,
        Alo + (size_t)(m0 + lr) * EE + lc * 8,
        Bhi + (size_t)(n0 + lr) * EE + lc * 8,
        Blo + (size_t)(n0 + lr) * EE + lc * 8
    };
    const uint32_t dst0 = sb + lr * ROWB + lc * 16;

    const uint32_t a_off = (wm + (lane & 15)) * ROWB + (lane >> 4) * 16;
    const uint32_t b_off = (wn + ((lane >> 4) << 3) + (lane & 7)) * ROWB
                         + ((lane >> 3) & 1) * 16;

    float d[2][8][4];
    #pragma unroll
    for (int mt = 0; mt < 2; mt++)
        #pragma unroll
        for (int nt = 0; nt < 8; nt++)
            #pragma unroll
            for (int i = 0; i < 4; i++) d[mt][nt][i] = 0.f;

    #pragma unroll
    for (int s = 0; s < 2; s++) {
        #pragma unroll
        for (int mat = 0; mat < 4; mat++) {
            #pragma unroll
            for (int p = 0; p < 2; p++) {
                uint32_t dst = dst0 + s * STGB + mat * MATB + p * 64 * ROWB;
                const void* g = gsrc[mat] + (size_t)p * 64 * EE + s * BKG;
                CP_ASYNC16(dst, g);
            }
        }
        CP_COMMIT();
    }

    for (int it = 0; it < NIT; it++) {
        if (it < NIT - 2)
            asm volatile("cp.async.wait_group 1;\n" ::: "memory");
        else
            asm volatile("cp.async.wait_group 0;\n" ::: "memory");
        __syncthreads();

        if (it + 2 < NIT) {
            int s = (it + 2) % GSTAGES;
            int k0 = (it + 2) * BKG;
            #pragma unroll
            for (int mat = 0; mat < 4; mat++) {
                #pragma unroll
                for (int p = 0; p < 2; p++) {
                    uint32_t dst = dst0 + s * STGB + mat * MATB + p * 64 * ROWB;
                    const void* g = gsrc[mat] + (size_t)p * 64 * EE + k0;
                    CP_ASYNC16(dst, g);
                }
            }
            CP_COMMIT();
        }

        const uint32_t st = sb + (it % GSTAGES) * STGB;
        #pragma unroll
        for (int kc = 0; kc < 2; kc++) {
            uint32_t ah[2][4], al[2][4], bh[4][4], bl[4][4];
            #pragma unroll
            for (int mt = 0; mt < 2; mt++) {
                ldsm_x4(ah[mt], st + OAH + a_off + mt * 16 * ROWB + kc * 32);
                ldsm_x4(al[mt], st + OAL + a_off + mt * 16 * ROWB + kc * 32);
            }
            #pragma unroll
            for (int nb = 0; nb < 4; nb++) {
                ldsm_x4(bh[nb], st + OBH + b_off + nb * 16 * ROWB + kc * 32);
                ldsm_x4(bl[nb], st + OBL + b_off + nb * 16 * ROWB + kc * 32);
            }
            #pragma unroll
            for (int mt = 0; mt < 2; mt++) {
                #pragma unroll
                for (int nt = 0; nt < 8; nt++) {
                    int nb = nt >> 1, sc = (nt & 1) * 2;
                    mma_bf16(d[mt][nt], ah[mt], bh[nb][sc], bh[nb][sc + 1]);
                    mma_bf16(d[mt][nt], ah[mt], bl[nb][sc], bl[nb][sc + 1]);
                    mma_bf16(d[mt][nt], al[mt], bh[nb][sc], bh[nb][sc + 1]);
                }
            }
        }
        __syncthreads();
    }

    if (EPI == 0) {
        // fp32 + bias epilogue (O projection)
        #pragma unroll
        for (int mt = 0; mt < 2; mt++) {
            int r = m0 + wm + mt * 16 + (lane >> 2);
            #pragma unroll
            for (int nt = 0; nt < 8; nt++) {
                int c = n0 + wn + nt * 8 + (lane & 3) * 2;
                float2 bb = *(const float2*)&b0[c];
                float2 o0 = {d[mt][nt][0] + bb.x, d[mt][nt][1] + bb.y};
                float2 o1 = {d[mt][nt][2] + bb.x, d[mt][nt][3] + bb.y};
                *(float2*)&Cf[(size_t)r * EE + c] = o0;
                *(float2*)&Cf[(size_t)(r + 8) * EE + c] = o1;
            }
        }
    } else {
        const float* bias = (z == 0) ? b0 : (z == 1) ? b1 : b2;
        // bias add into accumulators
        #pragma unroll
        for (int mt = 0; mt < 2; mt++)
            #pragma unroll
            for (int nt = 0; nt < 8; nt++) {
                float2 bb = *(const float2*)&bias[n0 + wn + nt * 8 + (lane & 3) * 2];
                d[mt][nt][0] += bb.x; d[mt][nt][1] += bb.y;
                d[mt][nt][2] += bb.x; d[mt][nt][3] += bb.y;
            }

        const int head = (n0 + wn) >> 6;
        __nv_bfloat16* Oh = (z == 0) ? O0h : (z == 1) ? O1h : O2h;
        __nv_bfloat16* Ol = (z == 0) ? O0l : (z == 1) ? O1l : O2l;

        if (z < 2) {
            // RoPE + hi/lo split, head-major store
            #pragma unroll
            for (int mt = 0; mt < 2; mt++) {
                #pragma unroll
                for (int rr = 0; rr < 2; rr++) {
                    int r = m0 + wm + mt * 16 + (lane >> 2) + rr * 8;
                    int b = r >> 10, s = r & (SS - 1);
                    size_t ob = ((size_t)(b * HH + head) * SS + s) * DD;
                    const float* cs = costab + s * 32;
                    const float* sn = sintab + s * 32;
                    #pragma unroll
                    for (int nt = 0; nt < 4; nt++) {
                        int dh = nt * 8 + (lane & 3) * 2;
                        float2 c2 = *(const float2*)&cs[dh];
                        float2 s2 = *(const float2*)&sn[dh];
                        float x1a = d[mt][nt][rr * 2 + 0];
                        float x1b = d[mt][nt][rr * 2 + 1];
                        float x2a = d[mt][nt + 4][rr * 2 + 0];
                        float x2b = d[mt][nt + 4][rr * 2 + 1];
                        float o1a = x1a * c2.x - x2a * s2.x;
                        float o1b = x1b * c2.y - x2b * s2.y;
                        float o2a = x2a * c2.x + x1a * s2.x;
                        float o2b = x2b * c2.y + x1b * s2.y;
                        uint32_t h1, l1, h2, l2;
                        pack_hilo(o1a, o1b, h1, l1);
                        pack_hilo(o2a, o2b, h2, l2);
                        *(uint32_t*)&Oh[ob + dh]      = h1;
                        *(uint32_t*)&Ol[ob + dh]      = l1;
                        *(uint32_t*)&Oh[ob + dh + 32] = h2;
                        *(uint32_t*)&Ol[ob + dh + 32] = l2;
                    }
                }
            }
        } else {
            // V: hi/lo split, head-major store
            #pragma unroll
            for (int mt = 0; mt < 2; mt++) {
                #pragma unroll
                for (int rr = 0; rr < 2; rr++) {
                    int r = m0 + wm + mt * 16 + (lane >> 2) + rr * 8;
                    int b = r >> 10, s = r & (SS - 1);
                    size_t ob = ((size_t)(b * HH + head) * SS + s) * DD;
                    #pragma unroll
                    for (int nt = 0; nt < 8; nt++) {
                        int dh = nt * 8 + (lane & 3) * 2;
                        uint32_t h, l;
                        pack_hilo(d[mt][nt][rr * 2 + 0],
                                  d[mt][nt][rr * 2 + 1], h, l);
                        *(uint32_t*)&Oh[ob + dh] = h;
                        *(uint32_t*)&Ol[ob + dh] = l;
                    }
                }
            }
        }
    }
}

// ---------------------------------------------------------------------------
// HMMA FlashAttention-2, bf16 hi/lo 3-pass; epilogue writes bf16 hi/lo AO.
// ---------------------------------------------------------------------------
#define ROWA 144
#define A_QTILE (128 * ROWA)
#define A_KV (64 * ROWA)
#define A_STG (4 * A_KV)
#define ATTN_SMEM (2 * A_QTILE + 2 * A_STG)   // 110592

__global__ __launch_bounds__(256) void attn_hmma_kernel(
    const __nv_bfloat16* __restrict__ Qh, const __nv_bfloat16* __restrict__ Ql,
    const __nv_bfloat16* __restrict__ Kh, const __nv_bfloat16* __restrict__ Kl,
    const __nv_bfloat16* __restrict__ Vh, const __nv_bfloat16* __restrict__ Vl,
    __nv_bfloat16* __restrict__ AOh, __nv_bfloat16* __restrict__ AOl)
{
    extern __shared__ char smraw[];
    const uint32_t sb = smem_u32(smraw);
    const int tid = threadIdx.x;
    const int wid = tid >> 5;
    const int lane = tid & 31;
    const int bh = blockIdx.y;
    const int b = bh >> 4, h = bh & (HH - 1);
    const int q0 = blockIdx.x * 128;

    const size_t hbase = (size_t)bh * SS * DD;
    const __nv_bfloat16* Qhp = Qh + hbase + (size_t)q0 * DD;
    const __nv_bfloat16* Qlp = Ql + hbase + (size_t)q0 * DD;
    const __nv_bfloat16* kv_src[4] = {Kh + hbase, Kl + hbase,
                                      Vh + hbase, Vl + hbase};

    const uint32_t sQh = sb, sQl = sb + A_QTILE;
    const uint32_t sKV = sb + 2 * A_QTILE;

    const int lr = tid >> 2;
    const int lc = tid & 3;

    #pragma unroll
    for (int p = 0; p < 2; p++) {
        int r = lr + p * 64;
        #pragma unroll
        for (int cc = 0; cc < 2; cc++) {
            int ch = lc + cc * 4;
            CP_ASYNC16(sQh + r * ROWA + ch * 16, Qhp + (size_t)r * DD + ch * 8);
            CP_ASYNC16(sQl + r * ROWA + ch * 16, Qlp + (size_t)r * DD + ch * 8);
        }
    }
    #pragma unroll
    for (int mat = 0; mat < 4; mat++) {
        #pragma unroll
        for (int cc = 0; cc < 2; cc++) {
            int ch = lc + cc * 4;
            CP_ASYNC16(sKV + mat * A_KV + lr * ROWA + ch * 16,
                       kv_src[mat] + (size_t)lr * DD + ch * 8);
        }
    }
    CP_COMMIT();
    #pragma unroll
    for (int mat = 0; mat < 4; mat++) {
        #pragma unroll
        for (int cc = 0; cc < 2; cc++) {
            int ch = lc + cc * 4;
            CP_ASYNC16(sKV + A_STG + mat * A_KV + lr * ROWA + ch * 16,
                       kv_src[mat] + (size_t)(64 + lr) * DD + ch * 8);
        }
    }
    CP_COMMIT();

    asm volatile("cp.async.wait_group 1;\n" ::: "memory");
    __syncthreads();

    const uint32_t a_off = (wid * 16 + (lane & 15)) * ROWA + (lane >> 4) * 16;
    uint32_t qh[4][4], ql[4][4];
    #pragma unroll
    for (int kk = 0; kk < 4; kk++) {
        ldsm_x4(qh[kk], sQh + a_off + kk * 32);
        ldsm_x4(ql[kk], sQl + a_off + kk * 32);
    }

    const uint32_t b_off = (((lane >> 4) << 3) + (lane & 7)) * ROWA
                         + ((lane >> 3) & 1) * 16;
    const uint32_t v_off = (lane & 15) * ROWA + (lane >> 4) * 16;

    float m0 = -CUDART_INF_F, m1 = -CUDART_INF_F, l0 = 0.f, l1 = 0.f;
    float o[8][4];
    #pragma unroll
    for (int j = 0; j < 8; j++)
        #pragma unroll
        for (int i = 0; i < 4; i++) o[j][i] = 0.f;

    const float scale = 0.125f;

    for (int it = 0; it < 16; it++) {
        if (it > 0) {
            if (it < 14)
                asm volatile("cp.async.wait_group 1;\n" ::: "memory");
            else
                asm volatile("cp.async.wait_group 0;\n" ::: "memory");
            __syncthreads();
        }
        const uint32_t st = sKV + (it & 1) * A_STG;

        float s[8][4];
        #pragma unroll
        for (int j = 0; j < 8; j++)
            #pragma unroll
            for (int i = 0; i < 4; i++) s[j][i] = 0.f;

        #pragma unroll
        for (int np = 0; np < 4; np++) {
            #pragma unroll
            for (int kk = 0; kk < 4; kk++) {
                uint32_t kh4[4], kl4[4];
                ldsm_x4(kh4, st + 0 * A_KV + b_off + np * 16 * ROWA + kk * 32);
                ldsm_x4(kl4, st + 1 * A_KV + b_off + np * 16 * ROWA + kk * 32);
                mma_bf16(s[np * 2 + 0], qh[kk], kh4[0], kh4[1]);
                mma_bf16(s[np * 2 + 1], qh[kk], kh4[2], kh4[3]);
                mma_bf16(s[np * 2 + 0], qh[kk], kl4[0], kl4[1]);
                mma_bf16(s[np * 2 + 1], qh[kk], kl4[2], kl4[3]);
                mma_bf16(s[np * 2 + 0], ql[kk], kh4[0], kh4[1]);
                mma_bf16(s[np * 2 + 1], ql[kk], kh4[2], kh4[3]);
            }
        }

        float rmax0 = -CUDART_INF_F, rmax1 = -CUDART_INF_F;
        #pragma unroll
        for (int j = 0; j < 8; j++) {
            #pragma unroll
            for (int i = 0; i < 4; i++) s[j][i] *= scale;
            rmax0 = fmaxf(rmax0, fmaxf(s[j][0], s[j][1]));
            rmax1 = fmaxf(rmax1, fmaxf(s[j][2], s[j][3]));
        }
        rmax0 = fmaxf(rmax0, __shfl_xor_sync(0xffffffffu, rmax0, 1));
        rmax0 = fmaxf(rmax0, __shfl_xor_sync(0xffffffffu, rmax0, 2));
        rmax1 = fmaxf(rmax1, __shfl_xor_sync(0xffffffffu, rmax1, 1));
        rmax1 = fmaxf(rmax1, __shfl_xor_sync(0xffffffffu, rmax1, 2));

        float mn0 = fmaxf(m0, rmax0), mn1 = fmaxf(m1, rmax1);
        float c0 = __expf(m0 - mn0), c1 = __expf(m1 - mn1);
        m0 = mn0; m1 = mn1;

        float rs0 = 0.f, rs1 = 0.f;
        #pragma unroll
        for (int j = 0; j < 8; j++) {
            s[j][0] = __expf(s[j][0] - mn0); rs0 += s[j][0];
            s[j][1] = __expf(s[j][1] - mn0); rs0 += s[j][1];
            s[j][2] = __expf(s[j][2] - mn1); rs1 += s[j][2];
            s[j][3] = __expf(s[j][3] - mn1); rs1 += s[j][3];
        }
        rs0 += __shfl_xor_sync(0xffffffffu, rs0, 1);
        rs0 += __shfl_xor_sync(0xffffffffu, rs0, 2);
        rs1 += __shfl_xor_sync(0xffffffffu, rs1, 1);
        rs1 += __shfl_xor_sync(0xffffffffu, rs1, 2);
        l0 = l0 * c0 + rs0;
        l1 = l1 * c1 + rs1;

        #pragma unroll
        for (int j = 0; j < 8; j++) {
            o[j][0] *= c0; o[j][1] *= c0;
            o[j][2] *= c1; o[j][3] *= c1;
        }

        #pragma unroll
        for (int kk = 0; kk < 4; kk++) {
            uint32_t ph[4], pl[4];
            pack_hilo(s[2 * kk][0],     s[2 * kk][1],     ph[0], pl[0]);
            pack_hilo(s[2 * kk][2],     s[2 * kk][3],     ph[1], pl[1]);
            pack_hilo(s[2 * kk + 1][0], s[2 * kk + 1][1], ph[2], pl[2]);
            pack_hilo(s[2 * kk + 1][2], s[2 * kk + 1][3], ph[3], pl[3]);
            #pragma unroll
            for (int np = 0; np < 4; np++) {
                uint32_t vh4[4], vl4[4];
                ldsm_x4_t(vh4, st + 2 * A_KV + v_off + kk * 16 * ROWA + np * 32);
                ldsm_x4_t(vl4, st + 3 * A_KV + v_off + kk * 16 * ROWA + np * 32);
                mma_bf16(o[np * 2 + 0], ph, vh4[0], vh4[1]);
                mma_bf16(o[np * 2 + 1], ph, vh4[2], vh4[3]);
                mma_bf16(o[np * 2 + 0], ph, vl4[0], vl4[1]);
                mma_bf16(o[np * 2 + 1], ph, vl4[2], vl4[3]);
                mma_bf16(o[np * 2 + 0], pl, vh4[0], vh4[1]);
                mma_bf16(o[np * 2 + 1], pl, vh4[2], vh4[3]);
            }
        }

        __syncthreads();
        if (it + 2 < 16) {
            uint32_t dstg = sKV + (it & 1) * A_STG;
            #pragma unroll
            for (int mat = 0; mat < 4; mat++) {
                #pragma unroll
                for (int cc = 0; cc < 2; cc++) {
                    int ch = lc + cc * 4;
                    CP_ASYNC16(dstg + mat * A_KV + lr * ROWA + ch * 16,
                               kv_src[mat] + (size_t)((it + 2) * 64 + lr) * DD + ch * 8);
                }
            }
            CP_COMMIT();
        }
    }

    // epilogue: normalize + hi/lo split -> AOh/AOl [b][s][h*64+d]
    float inv0 = 1.f / l0, inv1 = 1.f / l1;
    int r0 = q0 + wid * 16 + (lane >> 2);
    size_t base0 = (size_t)(b * SS + r0) * EE + h * DD;
    size_t base1 = base0 + (size_t)8 * EE;
    int c0l = (lane & 3) * 2;
    #pragma unroll
    for (int j = 0; j < 8; j++) {
        uint32_t h0, l0b, h1, l1b;
        pack_hilo(o[j][0] * inv0, o[j][1] * inv0, h0, l0b);
        pack_hilo(o[j][2] * inv1, o[j][3] * inv1, h1, l1b);
        *(uint32_t*)&AOh[base0 + j * 8 + c0l] = h0;
        *(uint32_t*)&AOl[base0 + j * 8 + c0l] = l0b;
        *(uint32_t*)&AOh[base1 + j * 8 + c0l] = h1;
        *(uint32_t*)&AOl[base1 + j * 8 + c0l] = l1b;
    }
}

// ---------------------------------------------------------------------------
// Launch
// ---------------------------------------------------------------------------
extern "C" void kernel_launch(void* const* d_in, const int* in_sizes, int n_in,
                              void* d_out, int out_size)
{
    const float* X   = (const float*)d_in[0];
    const float* rot = (const float*)d_in[1];
    const float* W[4]  = {(const float*)d_in[2], (const float*)d_in[4],
                          (const float*)d_in[6], (const float*)d_in[8]};
    const float* Bv[4] = {(const float*)d_in[3], (const float*)d_in[5],
                          (const float*)d_in[7], (const float*)d_in[9]};
    float* out = (float*)d_out;

    __nv_bfloat16 *Xhi, *Xlo, *AOhi, *AOlo, *Whi, *Wlo;
    __nv_bfloat16 *aQh, *aQl, *aKh, *aKl, *aVh, *aVl;
    float *ctab, *stab;
    cudaGetSymbolAddress((void**)&Xhi,  g_Xhi);
    cudaGetSymbolAddress((void**)&Xlo,  g_Xlo);
    cudaGetSymbolAddress((void**)&AOhi, g_AOhi);
    cudaGetSymbolAddress((void**)&AOlo, g_AOlo);
    cudaGetSymbolAddress((void**)&Whi,  g_Whi);
    cudaGetSymbolAddress((void**)&Wlo,  g_Wlo);
    cudaGetSymbolAddress((void**)&aQh,  g_aQh);
    cudaGetSymbolAddress((void**)&aQl,  g_aQl);
    cudaGetSymbolAddress((void**)&aKh,  g_aKh);
    cudaGetSymbolAddress((void**)&aKl,  g_aKl);
    cudaGetSymbolAddress((void**)&aVh,  g_aVh);
    cudaGetSymbolAddress((void**)&aVl,  g_aVl);
    cudaGetSymbolAddress((void**)&ctab, g_cos);
    cudaGetSymbolAddress((void**)&stab, g_sin);

    cudaFuncSetAttribute(gemm_hmma_t<0>,
                         cudaFuncAttributeMaxDynamicSharedMemorySize, GEMM_SMEM);
    cudaFuncSetAttribute(gemm_hmma_t<1>,
                         cudaFuncAttributeMaxDynamicSharedMemorySize, GEMM_SMEM);
    cudaFuncSetAttribute(attn_hmma_kernel,
                         cudaFuncAttributeMaxDynamicSharedMemorySize, ATTN_SMEM);

    rope_tab_kernel<<<(SS * 32 + 255) / 256, 256>>>(rot, ctab, stab);
    transpose_split_kernel<<<dim3(32, 32, 4), dim3(32, 32)>>>(
        W[0], W[1], W[2], W[3], Whi, Wlo);
    split_convert_kernel<<<(MM * EE / 4 + 255) / 256, 256>>>(
        X, Xhi, Xlo, MM * EE / 4);

    // Merged QKV projections with fused rope/split epilogues
    gemm_hmma_t<1><<<dim3(8, 64, 3), 256, GEMM_SMEM>>>(
        Xhi, Xlo, Whi, Wlo, Bv[0], Bv[1], Bv[2],
        nullptr, aQh, aQl, aKh, aKl, aVh, aVl, ctab, stab);

    attn_hmma_kernel<<<dim3(SS / 128, BB * HH), 256, ATTN_SMEM>>>(
        aQh, aQl, aKh, aKl, aVh, aVl, AOhi, AOlo);

    // O projection
    gemm_hmma_t<0><<<dim3(8, 64, 1), 256, GEMM_SMEM>>>(
        AOhi, AOlo, Whi + 3 * (size_t)EE * EE, Wlo + 3 * (size_t)EE * EE,
        Bv[3], nullptr, nullptr,
        out, nullptr, nullptr, nullptr, nullptr, nullptr, nullptr, ctab, stab);
}